// round 14
// baseline (speedup 1.0000x reference)
#include <cuda_runtime.h>
#include <cuda_bf16.h>
#include <math.h>
#include <stdint.h>

#define D 128
#define NMAX 50000
#define EMAX 800000
#define GMAX 512
#define BN_EPS 1e-5f
#define SLOPE 0.1f
#define CH 512
#define NCMAX 512

// ---------------- scratch (static device globals; no allocation) -------------
__device__ float    g_buf1[NMAX * D];
__device__ float    g_buf2[NMAX * D];
__device__ uint32_t g_WBh[3][D * 64];
__device__ uint32_t g_WBl[3][D * 64];
__device__ float    g_dinv[NMAX];
__device__ int      g_deg[NMAX];
__device__ int      g_rowstart[NMAX + 1];
__device__ int      g_wpos[NMAX];
__device__ int      g_srcs[EMAX];
__device__ float    g_ecoef[EMAX];
__device__ int      g_csum[NCMAX];
__device__ int      g_coff[NCMAX];
__device__ float    g_colsum[3][D * 32];
__device__ float    g_colsq[3][D * 32];
__device__ float    g_tsum[D * 32];
__device__ float    g_tsq[D * 32];
__device__ int      g_gcnt[GMAX];
__device__ int      g_gstart[GMAX + 1];
__device__ float    g_pooled[GMAX * D];
__device__ float    g_z1[GMAX * D];
__device__ int      g_scan_cnt = 0;
__device__ int      g_scan_flag = 0;
__device__ int      g_tail_cnt = 0;

// ---------------- helpers ------------------------------------------------------
__device__ __forceinline__ uint32_t smem_u32(const void* p) {
    uint32_t a;
    asm("{ .reg .u64 t; cvta.to.shared.u64 t, %1; cvt.u32.u64 %0, t; }" : "=r"(a) : "l"(p));
    return a;
}
__device__ __forceinline__ void ldsm_x4(uint32_t& r0, uint32_t& r1, uint32_t& r2,
                                        uint32_t& r3, uint32_t addr) {
    asm volatile("ldmatrix.sync.aligned.m8n8.x4.shared.b16 {%0,%1,%2,%3}, [%4];"
                 : "=r"(r0), "=r"(r1), "=r"(r2), "=r"(r3) : "r"(addr));
}
__device__ __forceinline__ void bf16_split_pack(float v0, float v1,
                                                uint32_t& h, uint32_t& l) {
    __nv_bfloat16 h0 = __float2bfloat16_rn(v0);
    __nv_bfloat16 h1 = __float2bfloat16_rn(v1);
    float r0 = v0 - __bfloat162float(h0);
    float r1 = v1 - __bfloat162float(h1);
    __nv_bfloat16 l0 = __float2bfloat16_rn(r0);
    __nv_bfloat16 l1 = __float2bfloat16_rn(r1);
    h = ((uint32_t)__bfloat16_as_ushort(h1) << 16) | __bfloat16_as_ushort(h0);
    l = ((uint32_t)__bfloat16_as_ushort(l1) << 16) | __bfloat16_as_ushort(l0);
}
__device__ __forceinline__ void mma_bf16(float* d, const uint32_t* a, const uint32_t* b) {
    asm volatile(
        "mma.sync.aligned.m16n8k16.row.col.f32.bf16.bf16.f32 "
        "{%0,%1,%2,%3}, {%4,%5,%6,%7}, {%8,%9}, {%0,%1,%2,%3};"
        : "+f"(d[0]), "+f"(d[1]), "+f"(d[2]), "+f"(d[3])
        : "r"(a[0]), "r"(a[1]), "r"(a[2]), "r"(a[3]), "r"(b[0]), "r"(b[1]));
}

// ---------------- bf16 3-term split GEMM (ldmatrix fragments) -----------------
#define ASTU 36
#define BSTU 68
#define SA_H 0
#define SA_L (128 * ASTU)
#define SB_H (2 * 128 * ASTU)
#define SB_L (SB_H + 128 * BSTU)
#define GEMM_U32 (SB_H + 2 * 128 * BSTU)

__global__ void __launch_bounds__(256, 2)
k_gemm_bf16(const float* __restrict__ A, const uint32_t* __restrict__ Bh,
            const uint32_t* __restrict__ Bl, float* __restrict__ C,
            int M, int apply_norm,
            const float* __restrict__ csum, const float* __restrict__ csq,
            const float* __restrict__ gamma, const float* __restrict__ beta,
            int Nn) {
    extern __shared__ uint32_t su[];
    __shared__ float s_scale[D];
    __shared__ float s_shift[D];
    uint32_t* sAh = su + SA_H;
    uint32_t* sAl = su + SA_L;
    uint32_t* sBh = su + SB_H;
    uint32_t* sBl = su + SB_L;

    const int tid = threadIdx.x;
    const int wid = tid >> 5;
    const int lid = tid & 31;
    const int wm  = wid & 1;
    const int wn  = wid >> 1;
    const int row0 = blockIdx.x * 128;

    const uint32_t su_a = smem_u32(su);
    const uint32_t sAh_a = su_a + SA_H * 4;
    const uint32_t sAl_a = su_a + SA_L * 4;
    const uint32_t sBh_a = su_a + SB_H * 4;
    const uint32_t sBl_a = su_a + SB_L * 4;

    const int arow  = lid & 15;
    const int akoff = (lid & 16) ? 4 : 0;
    uint32_t aoff[4];
#pragma unroll
    for (int mt = 0; mt < 4; mt++)
        aoff[mt] = (uint32_t)(((wm * 64 + mt * 16 + arow) * ASTU + akoff) * 4);
    const int brow  = wn * 32 + (lid & 7) + ((lid & 16) ? 8 : 0);
    const int bkoff = (lid & 8) ? 4 : 0;
    uint32_t boff[2];
#pragma unroll
    for (int q = 0; q < 2; q++)
        boff[q] = (uint32_t)(((brow + q * 16) * BSTU + bkoff) * 4);

    if (apply_norm && tid < D) {
        float ts = csum[tid * 32];
        float tq = csq[tid * 32];
        float mu = ts / (float)Nn;
        float var = tq / (float)Nn - mu * mu;
        float rinv = rsqrtf(var + BN_EPS);
        float sc = rinv * gamma[tid];
        s_scale[tid] = sc;
        s_shift[tid] = beta[tid] - mu * sc;
    }

#pragma unroll
    for (int i = 0; i < 8; i++) {
        int idx = tid + i * 256;
        int r = idx >> 4;
        int q = (idx & 15) * 4;
        *(uint4*)&sBh[r * BSTU + q] = *(const uint4*)&Bh[r * 64 + q];
        *(uint4*)&sBl[r * BSTU + q] = *(const uint4*)&Bl[r * 64 + q];
    }
    if (apply_norm) __syncthreads();

    float acc[4][4][4];
#pragma unroll
    for (int mt = 0; mt < 4; mt++)
#pragma unroll
        for (int nt = 0; nt < 4; nt++)
#pragma unroll
            for (int i = 0; i < 4; i++) acc[mt][nt][i] = 0.0f;

    for (int p = 0; p < 2; p++) {
        if (p) __syncthreads();
#pragma unroll
        for (int i = 0; i < 8; i++) {
            int idx = tid + i * 256;
            int r = idx >> 4;
            int c4 = (idx & 15) * 4;
            float4 v = make_float4(0.f, 0.f, 0.f, 0.f);
            if (row0 + r < M)
                v = *(const float4*)&A[(size_t)(row0 + r) * 128 + p * 64 + c4];
            if (apply_norm) {
                int cg = p * 64 + c4;
                v.x = v.x * s_scale[cg]     + s_shift[cg];
                v.y = v.y * s_scale[cg + 1] + s_shift[cg + 1];
                v.z = v.z * s_scale[cg + 2] + s_shift[cg + 2];
                v.w = v.w * s_scale[cg + 3] + s_shift[cg + 3];
                v.x = v.x > 0.f ? v.x : SLOPE * v.x;
                v.y = v.y > 0.f ? v.y : SLOPE * v.y;
                v.z = v.z > 0.f ? v.z : SLOPE * v.z;
                v.w = v.w > 0.f ? v.w : SLOPE * v.w;
            }
            uint2 hp, lp;
            bf16_split_pack(v.x, v.y, hp.x, lp.x);
            bf16_split_pack(v.z, v.w, hp.y, lp.y);
            *(uint2*)&sAh[r * ASTU + (c4 >> 1)] = hp;
            *(uint2*)&sAl[r * ASTU + (c4 >> 1)] = lp;
        }
        __syncthreads();

        const uint32_t pB = (uint32_t)(p * 32 * 4);
#pragma unroll
        for (int k16 = 0; k16 < 4; k16++) {
            const uint32_t kb4 = (uint32_t)(k16 * 8 * 4);
            uint32_t af[4][4], bh[4][2], bl[4][2];
#pragma unroll
            for (int mt = 0; mt < 4; mt++)
                ldsm_x4(af[mt][0], af[mt][1], af[mt][2], af[mt][3],
                        sAh_a + aoff[mt] + kb4);
            ldsm_x4(bh[0][0], bh[0][1], bh[1][0], bh[1][1], sBh_a + boff[0] + pB + kb4);
            ldsm_x4(bh[2][0], bh[2][1], bh[3][0], bh[3][1], sBh_a + boff[1] + pB + kb4);
            ldsm_x4(bl[0][0], bl[0][1], bl[1][0], bl[1][1], sBl_a + boff[0] + pB + kb4);
            ldsm_x4(bl[2][0], bl[2][1], bl[3][0], bl[3][1], sBl_a + boff[1] + pB + kb4);
#pragma unroll
            for (int mt = 0; mt < 4; mt++)
#pragma unroll
                for (int nt = 0; nt < 4; nt++)
                    mma_bf16(acc[mt][nt], af[mt], bh[nt]);
#pragma unroll
            for (int mt = 0; mt < 4; mt++)
#pragma unroll
                for (int nt = 0; nt < 4; nt++)
                    mma_bf16(acc[mt][nt], af[mt], bl[nt]);
#pragma unroll
            for (int mt = 0; mt < 4; mt++)
                ldsm_x4(af[mt][0], af[mt][1], af[mt][2], af[mt][3],
                        sAl_a + aoff[mt] + kb4);
#pragma unroll
            for (int mt = 0; mt < 4; mt++)
#pragma unroll
                for (int nt = 0; nt < 4; nt++)
                    mma_bf16(acc[mt][nt], af[mt], bh[nt]);
        }
    }
    __syncthreads();

    const int g  = lid >> 2;
    const int tg = lid & 3;
    float* sOut = (float*)su;
#pragma unroll
    for (int mt = 0; mt < 4; mt++) {
        int r0 = wm * 64 + mt * 16 + g;
#pragma unroll
        for (int nt = 0; nt < 4; nt++) {
            int c0 = wn * 32 + nt * 8 + tg * 2;
            sOut[r0 * 129 + c0]           = acc[mt][nt][0];
            sOut[r0 * 129 + c0 + 1]       = acc[mt][nt][1];
            sOut[(r0 + 8) * 129 + c0]     = acc[mt][nt][2];
            sOut[(r0 + 8) * 129 + c0 + 1] = acc[mt][nt][3];
        }
    }
    __syncthreads();

#pragma unroll 4
    for (int i = 0; i < 64; i++) {
        int idx = tid + i * 256;
        int r = idx >> 7;
        int c = idx & 127;
        if (row0 + r < M)
            C[(size_t)(row0 + r) * 128 + c] = sOut[r * 129 + c];
    }
}

// ---------------- weight prep + accumulator zeroing ---------------------------
__global__ void k_prep(const float* __restrict__ W1, const float* __restrict__ W2,
                       const float* __restrict__ W3) {
    __shared__ float s[32][33];
    const float* W = (blockIdx.z == 0) ? W1 : (blockIdx.z == 1) ? W2 : W3;
    uint32_t* Oh = g_WBh[blockIdx.z];
    uint32_t* Ol = g_WBl[blockIdx.z];
    int bx = blockIdx.x, by = blockIdx.y;
    int tx = threadIdx.x, ty = threadIdx.y;

    // zero BN accumulators: 48 blocks x 256 threads == 12288 == 3*D*32
    int bid = blockIdx.z * 16 + blockIdx.y * 4 + blockIdx.x;
    int gi = bid * 256 + ty * 32 + tx;
    g_colsum[0][gi] = 0.f;
    g_colsq[0][gi] = 0.f;
    if (gi < D * 32) { g_tsum[gi] = 0.f; g_tsq[gi] = 0.f; }

#pragma unroll
    for (int i = 0; i < 32; i += 8)
        s[ty + i][tx] = W[(by * 32 + ty + i) * 128 + bx * 32 + tx];
    __syncthreads();
#pragma unroll
    for (int p = ty; p < 16; p += 8) {
        float v0 = s[2 * p][tx];
        float v1 = s[2 * p + 1][tx];
        uint32_t h, l;
        bf16_split_pack(v0, v1, h, l);
        int o = (bx * 32 + tx) * 64 + by * 16 + p;
        Oh[o] = h;
        Ol[o] = l;
    }
}

// ---------------- init / count -------------------------------------------------
__global__ void k_zero(int N) {
    int i = blockIdx.x * blockDim.x + threadIdx.x;
    if (i < N) g_deg[i] = 0;
    if (i < GMAX) g_gcnt[i] = 0;
    if (i == 0) { g_scan_cnt = 0; g_scan_flag = 0; g_tail_cnt = 0; }
}
__global__ void k_count(const int* __restrict__ ei, const int* __restrict__ batch,
                        int E, int N) {
    int i = blockIdx.x * blockDim.x + threadIdx.x;
    if (i < E) atomicAdd(&g_deg[ei[E + i]], 1);
    if (i < N) atomicAdd(&g_gcnt[batch[i]], 1);
}

// ---------------- single fused scan (98 blocks, all resident, flag-spin) -------
__global__ void k_scan(int N, int NC, int G) {
    __shared__ int s[CH];
    __shared__ int ticket;
    int t = threadIdx.x;
    int i = blockIdx.x * CH + t;
    int v = (i < N) ? g_deg[i] : 0;
    s[t] = v;
    __syncthreads();
    for (int off = 1; off < CH; off <<= 1) {
        int x = (t >= off) ? s[t - off] : 0;
        __syncthreads();
        s[t] += x;
        __syncthreads();
    }
    int local = s[t];              // inclusive within block
    int btotal = s[CH - 1];
    if (t == 0) {
        g_csum[blockIdx.x] = btotal;
        __threadfence();
        ticket = atomicAdd(&g_scan_cnt, 1);
    }
    __syncthreads();
    if (ticket == gridDim.x - 1) {
        // last-arriving block scans chunk sums + graph ranges
        int cv = (t < NC) ? g_csum[t] : 0;
        s[t] = cv;
        __syncthreads();
        for (int off = 1; off < CH; off <<= 1) {
            int x = (t >= off) ? s[t - off] : 0;
            __syncthreads();
            s[t] += x;
            __syncthreads();
        }
        if (t < NC) g_coff[t] = s[t] - cv;
        if (t == NC - 1) g_rowstart[N] = s[t];
        __syncthreads();
        int gc = (t < G) ? g_gcnt[t] : 0;
        s[t] = gc;
        __syncthreads();
        for (int off = 1; off < CH; off <<= 1) {
            int x = (t >= off) ? s[t - off] : 0;
            __syncthreads();
            s[t] += x;
            __syncthreads();
        }
        if (t < G) g_gstart[t] = s[t] - gc;
        if (t == G - 1) g_gstart[G] = s[t];
        __threadfence();
        if (t == 0) atomicExch(&g_scan_flag, 1);
    } else {
        if (t == 0) {
            while (atomicAdd(&g_scan_flag, 0) == 0) __nanosleep(64);
        }
        __syncthreads();
    }
    int co = *((volatile int*)&g_coff[blockIdx.x]);
    if (i < N) {
        int excl = co + local - v;
        g_rowstart[i] = excl;
        g_wpos[i] = excl;
        g_dinv[i] = rsqrtf((float)v + 1.0f);
    }
}

__global__ void k_scatter(const int* __restrict__ ei, int E) {
    int e = blockIdx.x * blockDim.x + threadIdx.x;
    if (e < E) {
        int s = ei[e];
        int d = ei[E + e];
        int p = atomicAdd(&g_wpos[d], 1);
        g_srcs[p] = s;
        g_ecoef[p] = g_dinv[s] * g_dinv[d];
    }
}

// ---------------- edge aggregation + fused stats partials -----------------------
__global__ void k_aggregate(const float* __restrict__ h, const float* __restrict__ bias,
                            float* __restrict__ agg, int N, int layer) {
    __shared__ float s_sum[8][132];
    __shared__ float s_sq[8][132];
    const int wid = threadIdx.x >> 5;
    const int lane = threadIdx.x & 31;
    const int node = blockIdx.x * 8 + wid;
    const float4* __restrict__ h4 = (const float4*)h;

    float4 acc0 = make_float4(0.f, 0.f, 0.f, 0.f);
    if (node < N) {
        float di = g_dinv[node];
        float sc = di * di;
        float4 a = h4[(size_t)node * 32 + lane];
        acc0.x = a.x * sc; acc0.y = a.y * sc; acc0.z = a.z * sc; acc0.w = a.w * sc;
        float4 acc1 = make_float4(0.f, 0.f, 0.f, 0.f);
        float4 acc2 = make_float4(0.f, 0.f, 0.f, 0.f);
        float4 acc3 = make_float4(0.f, 0.f, 0.f, 0.f);

        int j = g_rowstart[node];
        int s1 = g_rowstart[node + 1];
        for (; j + 4 <= s1; j += 4) {
            int i0 = g_srcs[j], i1 = g_srcs[j + 1], i2 = g_srcs[j + 2], i3 = g_srcs[j + 3];
            float c0 = g_ecoef[j], c1 = g_ecoef[j + 1], c2 = g_ecoef[j + 2], c3 = g_ecoef[j + 3];
            float4 v0 = h4[(size_t)i0 * 32 + lane];
            float4 v1 = h4[(size_t)i1 * 32 + lane];
            float4 v2 = h4[(size_t)i2 * 32 + lane];
            float4 v3 = h4[(size_t)i3 * 32 + lane];
            acc0.x += v0.x * c0; acc0.y += v0.y * c0; acc0.z += v0.z * c0; acc0.w += v0.w * c0;
            acc1.x += v1.x * c1; acc1.y += v1.y * c1; acc1.z += v1.z * c1; acc1.w += v1.w * c1;
            acc2.x += v2.x * c2; acc2.y += v2.y * c2; acc2.z += v2.z * c2; acc2.w += v2.w * c2;
            acc3.x += v3.x * c3; acc3.y += v3.y * c3; acc3.z += v3.z * c3; acc3.w += v3.w * c3;
        }
        for (; j < s1; j++) {
            int s = g_srcs[j];
            float c = g_ecoef[j];
            float4 v = h4[(size_t)s * 32 + lane];
            acc0.x += v.x * c; acc0.y += v.y * c; acc0.z += v.z * c; acc0.w += v.w * c;
        }
        float4 b = ((const float4*)bias)[lane];
        acc0.x += acc1.x + acc2.x + acc3.x + b.x;
        acc0.y += acc1.y + acc2.y + acc3.y + b.y;
        acc0.z += acc1.z + acc2.z + acc3.z + b.z;
        acc0.w += acc1.w + acc2.w + acc3.w + b.w;
        ((float4*)agg)[(size_t)node * 32 + lane] = acc0;
    }

    int c4 = lane * 4;
    s_sum[wid][c4]     = acc0.x;
    s_sum[wid][c4 + 1] = acc0.y;
    s_sum[wid][c4 + 2] = acc0.z;
    s_sum[wid][c4 + 3] = acc0.w;
    s_sq[wid][c4]      = acc0.x * acc0.x;
    s_sq[wid][c4 + 1]  = acc0.y * acc0.y;
    s_sq[wid][c4 + 2]  = acc0.z * acc0.z;
    s_sq[wid][c4 + 3]  = acc0.w * acc0.w;
    __syncthreads();

    int c = threadIdx.x;
    if (c < D) {
        float ts = 0.f, tq = 0.f;
#pragma unroll
        for (int w = 0; w < 8; w++) { ts += s_sum[w][c]; tq += s_sq[w][c]; }
        atomicAdd(&g_colsum[layer][c * 32], ts);
        atomicAdd(&g_colsq[layer][c * 32], tq);
    }
}

// ---------------- fused tail: pool + FC1(+stats) + FC2 --------------------------
__device__ __forceinline__ void tail_barrier(int target) {
    __threadfence();
    __syncthreads();
    if (threadIdx.x == 0) {
        atomicAdd(&g_tail_cnt, 1);
        while (atomicAdd(&g_tail_cnt, 0) < target) __nanosleep(64);
    }
    __syncthreads();
}

__global__ void k_tail(const float* __restrict__ h, int G, int N,
                       const float* __restrict__ gamma2, const float* __restrict__ beta2,
                       const float* __restrict__ Wf1, const float* __restrict__ bf1,
                       const float* __restrict__ g4, const float* __restrict__ be4,
                       const float* __restrict__ Wf2, const float* __restrict__ bf2,
                       float* __restrict__ out) {
    __shared__ float s_scale[D], s_shift[D];
    __shared__ float As[32][36];
    __shared__ float Bs[32][132];
    __shared__ float s_sum[8][132], s_sq[8][132];
    const int tid = threadIdx.x;
    const int tx = tid & 31;
    const int ty = tid >> 5;
    const int nb = gridDim.x;
    const int row0 = blockIdx.x * 32;

    // ---- phase 1: pool (layer-3 BN from colsum[2], warp per graph) ----
    if (tid < D) {
        float ts = g_colsum[2][tid * 32];
        float tq = g_colsq[2][tid * 32];
        float mu = ts / (float)N;
        float var = tq / (float)N - mu * mu;
        float rinv = rsqrtf(var + BN_EPS);
        float sc = rinv * gamma2[tid];
        s_scale[tid] = sc;
        s_shift[tid] = beta2[tid] - mu * sc;
    }
    __syncthreads();
    {
        int warp = blockIdx.x * 8 + ty;
        if (warp < G) {
            const float4* h4 = (const float4*)h;
            int c = tx * 4;
            float4 sc4 = *(float4*)&s_scale[c];
            float4 sh4 = *(float4*)&s_shift[c];
            int s0 = g_gstart[warp], s1 = g_gstart[warp + 1];
            float4 acc = make_float4(0.f, 0.f, 0.f, 0.f);
            for (int r = s0; r < s1; r++) {
                float4 v = h4[(size_t)r * 32 + tx];
                float ax = v.x * sc4.x + sh4.x;
                float ay = v.y * sc4.y + sh4.y;
                float az = v.z * sc4.z + sh4.z;
                float aw = v.w * sc4.w + sh4.w;
                acc.x += ax > 0.f ? ax : SLOPE * ax;
                acc.y += ay > 0.f ? ay : SLOPE * ay;
                acc.z += az > 0.f ? az : SLOPE * az;
                acc.w += aw > 0.f ? aw : SLOPE * aw;
            }
            int cnt = s1 - s0;
            float inv = 1.0f / (float)(cnt > 0 ? cnt : 1);
            acc.x *= inv; acc.y *= inv; acc.z *= inv; acc.w *= inv;
            ((float4*)g_pooled)[(size_t)warp * 32 + tx] = acc;
        }
    }
    tail_barrier(nb);

    // ---- phase 2: FC1 (pooled @ Wf1 + bf1) + column stats ----
    if (row0 < G) {
        float acc[4][4];
#pragma unroll
        for (int i = 0; i < 4; i++)
#pragma unroll
            for (int j = 0; j < 4; j++) acc[i][j] = 0.0f;
        for (int k0 = 0; k0 < 128; k0 += 32) {
            __syncthreads();
            {
                int r = tid >> 3, c = (tid & 7) * 4;
                float4 v = make_float4(0.f, 0.f, 0.f, 0.f);
                if (row0 + r < G)
                    v = *(const float4*)&g_pooled[(size_t)(row0 + r) * 128 + k0 + c];
                As[r][c] = v.x; As[r][c + 1] = v.y; As[r][c + 2] = v.z; As[r][c + 3] = v.w;
            }
#pragma unroll
            for (int i = 0; i < 4; i++) {
                int idx = tid + i * 256;
                int r = idx >> 5, c = (idx & 31) * 4;
                float4 v = *(const float4*)&Wf1[(size_t)(k0 + r) * 128 + c];
                *(float4*)&Bs[r][c] = v;
            }
            __syncthreads();
#pragma unroll
            for (int k = 0; k < 32; k++) {
                float a[4];
#pragma unroll
                for (int i = 0; i < 4; i++) a[i] = As[ty * 4 + i][k];
                float4 b = *(const float4*)&Bs[k][tx * 4];
#pragma unroll
                for (int i = 0; i < 4; i++) {
                    acc[i][0] += a[i] * b.x;
                    acc[i][1] += a[i] * b.y;
                    acc[i][2] += a[i] * b.z;
                    acc[i][3] += a[i] * b.w;
                }
            }
        }
        float bx = bf1[tx * 4], by = bf1[tx * 4 + 1], bz = bf1[tx * 4 + 2], bw = bf1[tx * 4 + 3];
        float cs[4] = {0.f, 0.f, 0.f, 0.f};
        float cq[4] = {0.f, 0.f, 0.f, 0.f};
#pragma unroll
        for (int i = 0; i < 4; i++) {
            int r = row0 + ty * 4 + i;
            if (r < G) {
                float4 o;
                o.x = acc[i][0] + bx;
                o.y = acc[i][1] + by;
                o.z = acc[i][2] + bz;
                o.w = acc[i][3] + bw;
                *(float4*)&g_z1[(size_t)r * 128 + tx * 4] = o;
                cs[0] += o.x; cs[1] += o.y; cs[2] += o.z; cs[3] += o.w;
                cq[0] += o.x * o.x; cq[1] += o.y * o.y; cq[2] += o.z * o.z; cq[3] += o.w * o.w;
            }
        }
        __syncthreads();
#pragma unroll
        for (int j = 0; j < 4; j++) {
            s_sum[ty][tx * 4 + j] = cs[j];
            s_sq[ty][tx * 4 + j]  = cq[j];
        }
        __syncthreads();
        if (tid < D) {
            float ts = 0.f, tq = 0.f;
#pragma unroll
            for (int w = 0; w < 8; w++) { ts += s_sum[w][tid]; tq += s_sq[w][tid]; }
            atomicAdd(&g_tsum[tid * 32], ts);
            atomicAdd(&g_tsq[tid * 32], tq);
        }
    }
    tail_barrier(2 * nb);

    // ---- phase 3: FC2 with BN+leaky applied to z1 on load ----
    if (row0 < G) {
        if (tid < D) {
            float ts = g_tsum[tid * 32];
            float tq = g_tsq[tid * 32];
            float mu = ts / (float)G;
            float var = tq / (float)G - mu * mu;
            float rinv = rsqrtf(var + BN_EPS);
            float sc = rinv * g4[tid];
            s_scale[tid] = sc;
            s_shift[tid] = be4[tid] - mu * sc;
        }
        float acc[4][4];
#pragma unroll
        for (int i = 0; i < 4; i++)
#pragma unroll
            for (int j = 0; j < 4; j++) acc[i][j] = 0.0f;
        for (int k0 = 0; k0 < 128; k0 += 32) {
            __syncthreads();
            {
                int r = tid >> 3, c = (tid & 7) * 4;
                float4 v = make_float4(0.f, 0.f, 0.f, 0.f);
                if (row0 + r < G)
                    v = *(const float4*)&g_z1[(size_t)(row0 + r) * 128 + k0 + c];
                int cg = k0 + c;
                v.x = v.x * s_scale[cg]     + s_shift[cg];
                v.y = v.y * s_scale[cg + 1] + s_shift[cg + 1];
                v.z = v.z * s_scale[cg + 2] + s_shift[cg + 2];
                v.w = v.w * s_scale[cg + 3] + s_shift[cg + 3];
                v.x = v.x > 0.f ? v.x : SLOPE * v.x;
                v.y = v.y > 0.f ? v.y : SLOPE * v.y;
                v.z = v.z > 0.f ? v.z : SLOPE * v.z;
                v.w = v.w > 0.f ? v.w : SLOPE * v.w;
                As[r][c] = v.x; As[r][c + 1] = v.y; As[r][c + 2] = v.z; As[r][c + 3] = v.w;
            }
#pragma unroll
            for (int i = 0; i < 4; i++) {
                int idx = tid + i * 256;
                int r = idx >> 5, c = (idx & 31) * 4;
                float4 v = *(const float4*)&Wf2[(size_t)(k0 + r) * 128 + c];
                *(float4*)&Bs[r][c] = v;
            }
            __syncthreads();
#pragma unroll
            for (int k = 0; k < 32; k++) {
                float a[4];
#pragma unroll
                for (int i = 0; i < 4; i++) a[i] = As[ty * 4 + i][k];
                float4 b = *(const float4*)&Bs[k][tx * 4];
#pragma unroll
                for (int i = 0; i < 4; i++) {
                    acc[i][0] += a[i] * b.x;
                    acc[i][1] += a[i] * b.y;
                    acc[i][2] += a[i] * b.z;
                    acc[i][3] += a[i] * b.w;
                }
            }
        }
        float bx = bf2[tx * 4], by = bf2[tx * 4 + 1], bz = bf2[tx * 4 + 2], bw = bf2[tx * 4 + 3];
#pragma unroll
        for (int i = 0; i < 4; i++) {
            int r = row0 + ty * 4 + i;
            if (r < G) {
                float4 o;
                o.x = acc[i][0] + bx;
                o.y = acc[i][1] + by;
                o.z = acc[i][2] + bz;
                o.w = acc[i][3] + bw;
                *(float4*)&out[(size_t)r * 128 + tx * 4] = o;
            }
        }
    }
}

// ---------------- driver ---------------------------------------------------------
extern "C" void kernel_launch(void* const* d_in, const int* in_sizes, int n_in,
                              void* d_out, int out_size) {
    const float* x      = (const float*)d_in[0];
    const int*   ei     = (const int*)d_in[1];
    const int*   batch  = (const int*)d_in[2];
    const float* W1  = (const float*)d_in[4];
    const float* b1  = (const float*)d_in[5];
    const float* g1  = (const float*)d_in[6];
    const float* be1 = (const float*)d_in[7];
    const float* W2  = (const float*)d_in[8];
    const float* b2  = (const float*)d_in[9];
    const float* g2  = (const float*)d_in[10];
    const float* be2 = (const float*)d_in[11];
    const float* W3  = (const float*)d_in[12];
    const float* b3  = (const float*)d_in[13];
    const float* g3  = (const float*)d_in[14];
    const float* be3 = (const float*)d_in[15];
    const float* Wf1 = (const float*)d_in[16];
    const float* bf1 = (const float*)d_in[17];
    const float* g4  = (const float*)d_in[18];
    const float* be4 = (const float*)d_in[19];
    const float* Wf2 = (const float*)d_in[20];
    const float* bf2 = (const float*)d_in[21];

    int N = in_sizes[0] / D;
    int E = in_sizes[1] / 2;
    int G = out_size / D;
    if (N > NMAX || E > EMAX || G > GMAX) return;

    cudaFuncSetAttribute(k_gemm_bf16, cudaFuncAttributeMaxDynamicSharedMemorySize,
                         GEMM_U32 * 4);

    float *buf1, *buf2;
    float *csum, *csq;
    uint32_t *wbh, *wbl;
    cudaGetSymbolAddress((void**)&buf1, g_buf1);
    cudaGetSymbolAddress((void**)&buf2, g_buf2);
    cudaGetSymbolAddress((void**)&wbh, g_WBh);
    cudaGetSymbolAddress((void**)&wbl, g_WBl);
    cudaGetSymbolAddress((void**)&csum, g_colsum);
    cudaGetSymbolAddress((void**)&csq, g_colsq);

    int NC = (N + CH - 1) / CH;
    int mx = max(E, N);

    static cudaStream_t sB = nullptr;
    static cudaEvent_t evFork = nullptr, evCSR = nullptr;
    if (sB == nullptr) {
        cudaStreamCreateWithFlags(&sB, cudaStreamNonBlocking);
        cudaEventCreateWithFlags(&evFork, cudaEventDisableTiming);
        cudaEventCreateWithFlags(&evCSR, cudaEventDisableTiming);
    }

    cudaEventRecord(evFork, 0);
    cudaStreamWaitEvent(sB, evFork, 0);
    k_zero<<<(N + 255) / 256, 256, 0, sB>>>(N);
    k_count<<<(mx + 255) / 256, 256, 0, sB>>>(ei, batch, E, N);
    k_scan<<<NC, CH, 0, sB>>>(N, NC, G);
    k_scatter<<<(E + 255) / 256, 256, 0, sB>>>(ei, E);
    cudaEventRecord(evCSR, sB);

    const float* bs[3]  = {b1, b2, b3};
    const float* gs[3]  = {g1, g2, g3};
    const float* bes[3] = {be1, be2, be3};

    int tc_grid    = (N + 127) / 128;
    int agg_blocks = (N + 7) / 8;

    k_prep<<<dim3(4, 4, 3), dim3(32, 8)>>>(W1, W2, W3);
    k_gemm_bf16<<<tc_grid, 256, GEMM_U32 * 4>>>(x, wbh, wbl, buf1, N, 0,
                                                nullptr, nullptr, nullptr, nullptr, N);

    cudaStreamWaitEvent(0, evCSR, 0);

    for (int L = 0; L < 3; L++) {
        if (L > 0)
            k_gemm_bf16<<<tc_grid, 256, GEMM_U32 * 4>>>(
                buf2, wbh + L * D * 64, wbl + L * D * 64, buf1, N, 1,
                csum + (L - 1) * D * 32, csq + (L - 1) * D * 32, gs[L - 1], bes[L - 1], N);
        k_aggregate<<<agg_blocks, 256>>>(buf1, bs[L], buf2, N, L);
    }

    int tb = (G + 7) / 8;
    k_tail<<<tb, 256>>>(buf2, G, N, gs[2], bes[2], Wf1, bf1, g4, be4, Wf2, bf2,
                        (float*)d_out);
}

// round 15
// speedup vs baseline: 1.0043x; 1.0043x over previous
#include <cuda_runtime.h>
#include <cuda_bf16.h>
#include <math.h>
#include <stdint.h>

#define D 128
#define NMAX 50000
#define EMAX 800000
#define GMAX 512
#define BN_EPS 1e-5f
#define SLOPE 0.1f
#define CH 512
#define NCMAX 512

// ---------------- scratch (static device globals; no allocation) -------------
__device__ float    g_buf1[NMAX * D];
__device__ float    g_buf2[NMAX * D];
__device__ uint32_t g_WBh[3][D * 64];
__device__ uint32_t g_WBl[3][D * 64];
__device__ float    g_dinv[NMAX];
__device__ int      g_deg[NMAX];
__device__ int      g_rowstart[NMAX + 1];
__device__ int      g_wpos[NMAX];
__device__ int2     g_edge[EMAX];       // (src, coef bits) packed: 1 ST.64 in scatter
__device__ int      g_csum[NCMAX];
__device__ int      g_coff[NCMAX];
__device__ float    g_colsum[3][D * 32];
__device__ float    g_colsq[3][D * 32];
__device__ float    g_tsum[D * 32];
__device__ float    g_tsq[D * 32];
__device__ int      g_gcnt[GMAX];
__device__ int      g_gstart[GMAX + 1];
__device__ float    g_pooled[GMAX * D];
__device__ float    g_z1[GMAX * D];
__device__ int      g_scan_cnt = 0;
__device__ int      g_scan_flag = 0;
__device__ int      g_tail_cnt = 0;

// ---------------- helpers ------------------------------------------------------
__device__ __forceinline__ uint32_t smem_u32(const void* p) {
    uint32_t a;
    asm("{ .reg .u64 t; cvta.to.shared.u64 t, %1; cvt.u32.u64 %0, t; }" : "=r"(a) : "l"(p));
    return a;
}
__device__ __forceinline__ void ldsm_x4(uint32_t& r0, uint32_t& r1, uint32_t& r2,
                                        uint32_t& r3, uint32_t addr) {
    asm volatile("ldmatrix.sync.aligned.m8n8.x4.shared.b16 {%0,%1,%2,%3}, [%4];"
                 : "=r"(r0), "=r"(r1), "=r"(r2), "=r"(r3) : "r"(addr));
}
__device__ __forceinline__ void bf16_split_pack(float v0, float v1,
                                                uint32_t& h, uint32_t& l) {
    __nv_bfloat16 h0 = __float2bfloat16_rn(v0);
    __nv_bfloat16 h1 = __float2bfloat16_rn(v1);
    float r0 = v0 - __bfloat162float(h0);
    float r1 = v1 - __bfloat162float(h1);
    __nv_bfloat16 l0 = __float2bfloat16_rn(r0);
    __nv_bfloat16 l1 = __float2bfloat16_rn(r1);
    h = ((uint32_t)__bfloat16_as_ushort(h1) << 16) | __bfloat16_as_ushort(h0);
    l = ((uint32_t)__bfloat16_as_ushort(l1) << 16) | __bfloat16_as_ushort(l0);
}
__device__ __forceinline__ void mma_bf16(float* d, const uint32_t* a, const uint32_t* b) {
    asm volatile(
        "mma.sync.aligned.m16n8k16.row.col.f32.bf16.bf16.f32 "
        "{%0,%1,%2,%3}, {%4,%5,%6,%7}, {%8,%9}, {%0,%1,%2,%3};"
        : "+f"(d[0]), "+f"(d[1]), "+f"(d[2]), "+f"(d[3])
        : "r"(a[0]), "r"(a[1]), "r"(a[2]), "r"(a[3]), "r"(b[0]), "r"(b[1]));
}

// ---------------- bf16 3-term split GEMM (ldmatrix fragments) -----------------
#define ASTU 36
#define BSTU 68
#define SA_H 0
#define SA_L (128 * ASTU)
#define SB_H (2 * 128 * ASTU)
#define SB_L (SB_H + 128 * BSTU)
#define GEMM_U32 (SB_H + 2 * 128 * BSTU)

__global__ void __launch_bounds__(256, 2)
k_gemm_bf16(const float* __restrict__ A, const uint32_t* __restrict__ Bh,
            const uint32_t* __restrict__ Bl, float* __restrict__ C,
            int M, int apply_norm,
            const float* __restrict__ csum, const float* __restrict__ csq,
            const float* __restrict__ gamma, const float* __restrict__ beta,
            int Nn) {
    extern __shared__ uint32_t su[];
    __shared__ float s_scale[D];
    __shared__ float s_shift[D];
    uint32_t* sAh = su + SA_H;
    uint32_t* sAl = su + SA_L;
    uint32_t* sBh = su + SB_H;
    uint32_t* sBl = su + SB_L;

    const int tid = threadIdx.x;
    const int wid = tid >> 5;
    const int lid = tid & 31;
    const int wm  = wid & 1;
    const int wn  = wid >> 1;
    const int row0 = blockIdx.x * 128;

    const uint32_t su_a = smem_u32(su);
    const uint32_t sAh_a = su_a + SA_H * 4;
    const uint32_t sAl_a = su_a + SA_L * 4;
    const uint32_t sBh_a = su_a + SB_H * 4;
    const uint32_t sBl_a = su_a + SB_L * 4;

    const int arow  = lid & 15;
    const int akoff = (lid & 16) ? 4 : 0;
    uint32_t aoff[4];
#pragma unroll
    for (int mt = 0; mt < 4; mt++)
        aoff[mt] = (uint32_t)(((wm * 64 + mt * 16 + arow) * ASTU + akoff) * 4);
    const int brow  = wn * 32 + (lid & 7) + ((lid & 16) ? 8 : 0);
    const int bkoff = (lid & 8) ? 4 : 0;
    uint32_t boff[2];
#pragma unroll
    for (int q = 0; q < 2; q++)
        boff[q] = (uint32_t)(((brow + q * 16) * BSTU + bkoff) * 4);

    if (apply_norm && tid < D) {
        float ts = csum[tid * 32];
        float tq = csq[tid * 32];
        float mu = ts / (float)Nn;
        float var = tq / (float)Nn - mu * mu;
        float rinv = rsqrtf(var + BN_EPS);
        float sc = rinv * gamma[tid];
        s_scale[tid] = sc;
        s_shift[tid] = beta[tid] - mu * sc;
    }

#pragma unroll
    for (int i = 0; i < 8; i++) {
        int idx = tid + i * 256;
        int r = idx >> 4;
        int q = (idx & 15) * 4;
        *(uint4*)&sBh[r * BSTU + q] = *(const uint4*)&Bh[r * 64 + q];
        *(uint4*)&sBl[r * BSTU + q] = *(const uint4*)&Bl[r * 64 + q];
    }
    if (apply_norm) __syncthreads();

    float acc[4][4][4];
#pragma unroll
    for (int mt = 0; mt < 4; mt++)
#pragma unroll
        for (int nt = 0; nt < 4; nt++)
#pragma unroll
            for (int i = 0; i < 4; i++) acc[mt][nt][i] = 0.0f;

    for (int p = 0; p < 2; p++) {
        if (p) __syncthreads();
#pragma unroll
        for (int i = 0; i < 8; i++) {
            int idx = tid + i * 256;
            int r = idx >> 4;
            int c4 = (idx & 15) * 4;
            float4 v = make_float4(0.f, 0.f, 0.f, 0.f);
            if (row0 + r < M)
                v = *(const float4*)&A[(size_t)(row0 + r) * 128 + p * 64 + c4];
            if (apply_norm) {
                int cg = p * 64 + c4;
                v.x = v.x * s_scale[cg]     + s_shift[cg];
                v.y = v.y * s_scale[cg + 1] + s_shift[cg + 1];
                v.z = v.z * s_scale[cg + 2] + s_shift[cg + 2];
                v.w = v.w * s_scale[cg + 3] + s_shift[cg + 3];
                v.x = v.x > 0.f ? v.x : SLOPE * v.x;
                v.y = v.y > 0.f ? v.y : SLOPE * v.y;
                v.z = v.z > 0.f ? v.z : SLOPE * v.z;
                v.w = v.w > 0.f ? v.w : SLOPE * v.w;
            }
            uint2 hp, lp;
            bf16_split_pack(v.x, v.y, hp.x, lp.x);
            bf16_split_pack(v.z, v.w, hp.y, lp.y);
            *(uint2*)&sAh[r * ASTU + (c4 >> 1)] = hp;
            *(uint2*)&sAl[r * ASTU + (c4 >> 1)] = lp;
        }
        __syncthreads();

        const uint32_t pB = (uint32_t)(p * 32 * 4);
#pragma unroll
        for (int k16 = 0; k16 < 4; k16++) {
            const uint32_t kb4 = (uint32_t)(k16 * 8 * 4);
            uint32_t af[4][4], bh[4][2], bl[4][2];
#pragma unroll
            for (int mt = 0; mt < 4; mt++)
                ldsm_x4(af[mt][0], af[mt][1], af[mt][2], af[mt][3],
                        sAh_a + aoff[mt] + kb4);
            ldsm_x4(bh[0][0], bh[0][1], bh[1][0], bh[1][1], sBh_a + boff[0] + pB + kb4);
            ldsm_x4(bh[2][0], bh[2][1], bh[3][0], bh[3][1], sBh_a + boff[1] + pB + kb4);
            ldsm_x4(bl[0][0], bl[0][1], bl[1][0], bl[1][1], sBl_a + boff[0] + pB + kb4);
            ldsm_x4(bl[2][0], bl[2][1], bl[3][0], bl[3][1], sBl_a + boff[1] + pB + kb4);
#pragma unroll
            for (int mt = 0; mt < 4; mt++)
#pragma unroll
                for (int nt = 0; nt < 4; nt++)
                    mma_bf16(acc[mt][nt], af[mt], bh[nt]);
#pragma unroll
            for (int mt = 0; mt < 4; mt++)
#pragma unroll
                for (int nt = 0; nt < 4; nt++)
                    mma_bf16(acc[mt][nt], af[mt], bl[nt]);
#pragma unroll
            for (int mt = 0; mt < 4; mt++)
                ldsm_x4(af[mt][0], af[mt][1], af[mt][2], af[mt][3],
                        sAl_a + aoff[mt] + kb4);
#pragma unroll
            for (int mt = 0; mt < 4; mt++)
#pragma unroll
                for (int nt = 0; nt < 4; nt++)
                    mma_bf16(acc[mt][nt], af[mt], bh[nt]);
        }
    }
    __syncthreads();

    const int g  = lid >> 2;
    const int tg = lid & 3;
    float* sOut = (float*)su;
#pragma unroll
    for (int mt = 0; mt < 4; mt++) {
        int r0 = wm * 64 + mt * 16 + g;
#pragma unroll
        for (int nt = 0; nt < 4; nt++) {
            int c0 = wn * 32 + nt * 8 + tg * 2;
            sOut[r0 * 129 + c0]           = acc[mt][nt][0];
            sOut[r0 * 129 + c0 + 1]       = acc[mt][nt][1];
            sOut[(r0 + 8) * 129 + c0]     = acc[mt][nt][2];
            sOut[(r0 + 8) * 129 + c0 + 1] = acc[mt][nt][3];
        }
    }
    __syncthreads();

#pragma unroll 4
    for (int i = 0; i < 64; i++) {
        int idx = tid + i * 256;
        int r = idx >> 7;
        int c = idx & 127;
        if (row0 + r < M)
            C[(size_t)(row0 + r) * 128 + c] = sOut[r * 129 + c];
    }
}

// ---------------- weight prep + accumulator zeroing ---------------------------
__global__ void k_prep(const float* __restrict__ W1, const float* __restrict__ W2,
                       const float* __restrict__ W3) {
    __shared__ float s[32][33];
    const float* W = (blockIdx.z == 0) ? W1 : (blockIdx.z == 1) ? W2 : W3;
    uint32_t* Oh = g_WBh[blockIdx.z];
    uint32_t* Ol = g_WBl[blockIdx.z];
    int bx = blockIdx.x, by = blockIdx.y;
    int tx = threadIdx.x, ty = threadIdx.y;

    int bid = blockIdx.z * 16 + blockIdx.y * 4 + blockIdx.x;
    int gi = bid * 256 + ty * 32 + tx;
    g_colsum[0][gi] = 0.f;
    g_colsq[0][gi] = 0.f;
    if (gi < D * 32) { g_tsum[gi] = 0.f; g_tsq[gi] = 0.f; }

#pragma unroll
    for (int i = 0; i < 32; i += 8)
        s[ty + i][tx] = W[(by * 32 + ty + i) * 128 + bx * 32 + tx];
    __syncthreads();
#pragma unroll
    for (int p = ty; p < 16; p += 8) {
        float v0 = s[2 * p][tx];
        float v1 = s[2 * p + 1][tx];
        uint32_t h, l;
        bf16_split_pack(v0, v1, h, l);
        int o = (bx * 32 + tx) * 64 + by * 16 + p;
        Oh[o] = h;
        Ol[o] = l;
    }
}

// ---------------- init / count -------------------------------------------------
__global__ void k_zero(int N) {
    int i = blockIdx.x * blockDim.x + threadIdx.x;
    if (i < N) g_deg[i] = 0;
    if (i < GMAX) g_gcnt[i] = 0;
    if (i == 0) { g_scan_cnt = 0; g_scan_flag = 0; g_tail_cnt = 0; }
}
__global__ void k_count(const int* __restrict__ ei, const int* __restrict__ batch,
                        int E, int N) {
    int i = blockIdx.x * blockDim.x + threadIdx.x;
    if (i < E) atomicAdd(&g_deg[ei[E + i]], 1);
    if (i < N) atomicAdd(&g_gcnt[batch[i]], 1);
}

// ---------------- single fused scan (98 blocks, all resident, flag-spin) -------
__global__ void k_scan(int N, int NC, int G) {
    __shared__ int s[CH];
    __shared__ int ticket;
    int t = threadIdx.x;
    int i = blockIdx.x * CH + t;
    int v = (i < N) ? g_deg[i] : 0;
    s[t] = v;
    __syncthreads();
    for (int off = 1; off < CH; off <<= 1) {
        int x = (t >= off) ? s[t - off] : 0;
        __syncthreads();
        s[t] += x;
        __syncthreads();
    }
    int local = s[t];
    int btotal = s[CH - 1];
    if (t == 0) {
        g_csum[blockIdx.x] = btotal;
        __threadfence();
        ticket = atomicAdd(&g_scan_cnt, 1);
    }
    __syncthreads();
    if (ticket == gridDim.x - 1) {
        int cv = (t < NC) ? g_csum[t] : 0;
        s[t] = cv;
        __syncthreads();
        for (int off = 1; off < CH; off <<= 1) {
            int x = (t >= off) ? s[t - off] : 0;
            __syncthreads();
            s[t] += x;
            __syncthreads();
        }
        if (t < NC) g_coff[t] = s[t] - cv;
        if (t == NC - 1) g_rowstart[N] = s[t];
        __syncthreads();
        int gc = (t < G) ? g_gcnt[t] : 0;
        s[t] = gc;
        __syncthreads();
        for (int off = 1; off < CH; off <<= 1) {
            int x = (t >= off) ? s[t - off] : 0;
            __syncthreads();
            s[t] += x;
            __syncthreads();
        }
        if (t < G) g_gstart[t] = s[t] - gc;
        if (t == G - 1) g_gstart[G] = s[t];
        __threadfence();
        if (t == 0) atomicExch(&g_scan_flag, 1);
    } else {
        if (t == 0) {
            while (atomicAdd(&g_scan_flag, 0) == 0) __nanosleep(64);
        }
        __syncthreads();
    }
    int co = *((volatile int*)&g_coff[blockIdx.x]);
    if (i < N) {
        int excl = co + local - v;
        g_rowstart[i] = excl;
        g_wpos[i] = excl;
        g_dinv[i] = rsqrtf((float)v + 1.0f);
    }
}

// ---------------- scatter: packed 8-byte payload ------------------------------
__global__ void k_scatter(const int* __restrict__ ei, int E) {
    int e = blockIdx.x * blockDim.x + threadIdx.x;
    if (e < E) {
        int s = ei[e];
        int d = ei[E + e];
        int p = atomicAdd(&g_wpos[d], 1);
        int2 pk;
        pk.x = s;
        pk.y = __float_as_int(g_dinv[s] * g_dinv[d]);
        g_edge[p] = pk;   // single ST.64
    }
}

// ---------------- edge aggregation + fused stats partials -----------------------
__global__ void k_aggregate(const float* __restrict__ h, const float* __restrict__ bias,
                            float* __restrict__ agg, int N, int layer) {
    __shared__ float s_sum[8][132];
    __shared__ float s_sq[8][132];
    const int wid = threadIdx.x >> 5;
    const int lane = threadIdx.x & 31;
    const int node = blockIdx.x * 8 + wid;
    const float4* __restrict__ h4 = (const float4*)h;

    float4 acc0 = make_float4(0.f, 0.f, 0.f, 0.f);
    if (node < N) {
        float di = g_dinv[node];
        float sc = di * di;
        float4 a = h4[(size_t)node * 32 + lane];
        acc0.x = a.x * sc; acc0.y = a.y * sc; acc0.z = a.z * sc; acc0.w = a.w * sc;
        float4 acc1 = make_float4(0.f, 0.f, 0.f, 0.f);
        float4 acc2 = make_float4(0.f, 0.f, 0.f, 0.f);
        float4 acc3 = make_float4(0.f, 0.f, 0.f, 0.f);

        int j = g_rowstart[node];
        int s1 = g_rowstart[node + 1];
        for (; j + 4 <= s1; j += 4) {
            int2 e0 = g_edge[j];
            int2 e1 = g_edge[j + 1];
            int2 e2 = g_edge[j + 2];
            int2 e3 = g_edge[j + 3];
            float4 v0 = h4[(size_t)e0.x * 32 + lane];
            float4 v1 = h4[(size_t)e1.x * 32 + lane];
            float4 v2 = h4[(size_t)e2.x * 32 + lane];
            float4 v3 = h4[(size_t)e3.x * 32 + lane];
            float c0 = __int_as_float(e0.y);
            float c1 = __int_as_float(e1.y);
            float c2 = __int_as_float(e2.y);
            float c3 = __int_as_float(e3.y);
            acc0.x += v0.x * c0; acc0.y += v0.y * c0; acc0.z += v0.z * c0; acc0.w += v0.w * c0;
            acc1.x += v1.x * c1; acc1.y += v1.y * c1; acc1.z += v1.z * c1; acc1.w += v1.w * c1;
            acc2.x += v2.x * c2; acc2.y += v2.y * c2; acc2.z += v2.z * c2; acc2.w += v2.w * c2;
            acc3.x += v3.x * c3; acc3.y += v3.y * c3; acc3.z += v3.z * c3; acc3.w += v3.w * c3;
        }
        for (; j < s1; j++) {
            int2 e0 = g_edge[j];
            float c = __int_as_float(e0.y);
            float4 v = h4[(size_t)e0.x * 32 + lane];
            acc0.x += v.x * c; acc0.y += v.y * c; acc0.z += v.z * c; acc0.w += v.w * c;
        }
        float4 b = ((const float4*)bias)[lane];
        acc0.x += acc1.x + acc2.x + acc3.x + b.x;
        acc0.y += acc1.y + acc2.y + acc3.y + b.y;
        acc0.z += acc1.z + acc2.z + acc3.z + b.z;
        acc0.w += acc1.w + acc2.w + acc3.w + b.w;
        ((float4*)agg)[(size_t)node * 32 + lane] = acc0;
    }

    int c4 = lane * 4;
    s_sum[wid][c4]     = acc0.x;
    s_sum[wid][c4 + 1] = acc0.y;
    s_sum[wid][c4 + 2] = acc0.z;
    s_sum[wid][c4 + 3] = acc0.w;
    s_sq[wid][c4]      = acc0.x * acc0.x;
    s_sq[wid][c4 + 1]  = acc0.y * acc0.y;
    s_sq[wid][c4 + 2]  = acc0.z * acc0.z;
    s_sq[wid][c4 + 3]  = acc0.w * acc0.w;
    __syncthreads();

    int c = threadIdx.x;
    if (c < D) {
        float ts = 0.f, tq = 0.f;
#pragma unroll
        for (int w = 0; w < 8; w++) { ts += s_sum[w][c]; tq += s_sq[w][c]; }
        atomicAdd(&g_colsum[layer][c * 32], ts);
        atomicAdd(&g_colsq[layer][c * 32], tq);
    }
}

// ---------------- fused tail: pool + FC1(+stats) + FC2 --------------------------
__device__ __forceinline__ void tail_barrier(int target) {
    __threadfence();
    __syncthreads();
    if (threadIdx.x == 0) {
        atomicAdd(&g_tail_cnt, 1);
        while (atomicAdd(&g_tail_cnt, 0) < target) __nanosleep(64);
    }
    __syncthreads();
}

__global__ void k_tail(const float* __restrict__ h, int G, int N,
                       const float* __restrict__ gamma2, const float* __restrict__ beta2,
                       const float* __restrict__ Wf1, const float* __restrict__ bf1,
                       const float* __restrict__ g4, const float* __restrict__ be4,
                       const float* __restrict__ Wf2, const float* __restrict__ bf2,
                       float* __restrict__ out) {
    __shared__ float s_scale[D], s_shift[D];
    __shared__ float As[32][36];
    __shared__ float Bs[32][132];
    __shared__ float s_sum[8][132], s_sq[8][132];
    const int tid = threadIdx.x;
    const int tx = tid & 31;
    const int ty = tid >> 5;
    const int nb = gridDim.x;
    const int row0 = blockIdx.x * 32;

    if (tid < D) {
        float ts = g_colsum[2][tid * 32];
        float tq = g_colsq[2][tid * 32];
        float mu = ts / (float)N;
        float var = tq / (float)N - mu * mu;
        float rinv = rsqrtf(var + BN_EPS);
        float sc = rinv * gamma2[tid];
        s_scale[tid] = sc;
        s_shift[tid] = beta2[tid] - mu * sc;
    }
    __syncthreads();
    {
        int warp = blockIdx.x * 8 + ty;
        if (warp < G) {
            const float4* h4 = (const float4*)h;
            int c = tx * 4;
            float4 sc4 = *(float4*)&s_scale[c];
            float4 sh4 = *(float4*)&s_shift[c];
            int s0 = g_gstart[warp], s1 = g_gstart[warp + 1];
            float4 acc = make_float4(0.f, 0.f, 0.f, 0.f);
            for (int r = s0; r < s1; r++) {
                float4 v = h4[(size_t)r * 32 + tx];
                float ax = v.x * sc4.x + sh4.x;
                float ay = v.y * sc4.y + sh4.y;
                float az = v.z * sc4.z + sh4.z;
                float aw = v.w * sc4.w + sh4.w;
                acc.x += ax > 0.f ? ax : SLOPE * ax;
                acc.y += ay > 0.f ? ay : SLOPE * ay;
                acc.z += az > 0.f ? az : SLOPE * az;
                acc.w += aw > 0.f ? aw : SLOPE * aw;
            }
            int cnt = s1 - s0;
            float inv = 1.0f / (float)(cnt > 0 ? cnt : 1);
            acc.x *= inv; acc.y *= inv; acc.z *= inv; acc.w *= inv;
            ((float4*)g_pooled)[(size_t)warp * 32 + tx] = acc;
        }
    }
    tail_barrier(nb);

    if (row0 < G) {
        float acc[4][4];
#pragma unroll
        for (int i = 0; i < 4; i++)
#pragma unroll
            for (int j = 0; j < 4; j++) acc[i][j] = 0.0f;
        for (int k0 = 0; k0 < 128; k0 += 32) {
            __syncthreads();
            {
                int r = tid >> 3, c = (tid & 7) * 4;
                float4 v = make_float4(0.f, 0.f, 0.f, 0.f);
                if (row0 + r < G)
                    v = *(const float4*)&g_pooled[(size_t)(row0 + r) * 128 + k0 + c];
                As[r][c] = v.x; As[r][c + 1] = v.y; As[r][c + 2] = v.z; As[r][c + 3] = v.w;
            }
#pragma unroll
            for (int i = 0; i < 4; i++) {
                int idx = tid + i * 256;
                int r = idx >> 5, c = (idx & 31) * 4;
                float4 v = *(const float4*)&Wf1[(size_t)(k0 + r) * 128 + c];
                *(float4*)&Bs[r][c] = v;
            }
            __syncthreads();
#pragma unroll
            for (int k = 0; k < 32; k++) {
                float a[4];
#pragma unroll
                for (int i = 0; i < 4; i++) a[i] = As[ty * 4 + i][k];
                float4 b = *(const float4*)&Bs[k][tx * 4];
#pragma unroll
                for (int i = 0; i < 4; i++) {
                    acc[i][0] += a[i] * b.x;
                    acc[i][1] += a[i] * b.y;
                    acc[i][2] += a[i] * b.z;
                    acc[i][3] += a[i] * b.w;
                }
            }
        }
        float bx = bf1[tx * 4], by = bf1[tx * 4 + 1], bz = bf1[tx * 4 + 2], bw = bf1[tx * 4 + 3];
        float cs[4] = {0.f, 0.f, 0.f, 0.f};
        float cq[4] = {0.f, 0.f, 0.f, 0.f};
#pragma unroll
        for (int i = 0; i < 4; i++) {
            int r = row0 + ty * 4 + i;
            if (r < G) {
                float4 o;
                o.x = acc[i][0] + bx;
                o.y = acc[i][1] + by;
                o.z = acc[i][2] + bz;
                o.w = acc[i][3] + bw;
                *(float4*)&g_z1[(size_t)r * 128 + tx * 4] = o;
                cs[0] += o.x; cs[1] += o.y; cs[2] += o.z; cs[3] += o.w;
                cq[0] += o.x * o.x; cq[1] += o.y * o.y; cq[2] += o.z * o.z; cq[3] += o.w * o.w;
            }
        }
        __syncthreads();
#pragma unroll
        for (int j = 0; j < 4; j++) {
            s_sum[ty][tx * 4 + j] = cs[j];
            s_sq[ty][tx * 4 + j]  = cq[j];
        }
        __syncthreads();
        if (tid < D) {
            float ts = 0.f, tq = 0.f;
#pragma unroll
            for (int w = 0; w < 8; w++) { ts += s_sum[w][tid]; tq += s_sq[w][tid]; }
            atomicAdd(&g_tsum[tid * 32], ts);
            atomicAdd(&g_tsq[tid * 32], tq);
        }
    }
    tail_barrier(2 * nb);

    if (row0 < G) {
        if (tid < D) {
            float ts = g_tsum[tid * 32];
            float tq = g_tsq[tid * 32];
            float mu = ts / (float)G;
            float var = tq / (float)G - mu * mu;
            float rinv = rsqrtf(var + BN_EPS);
            float sc = rinv * g4[tid];
            s_scale[tid] = sc;
            s_shift[tid] = be4[tid] - mu * sc;
        }
        float acc[4][4];
#pragma unroll
        for (int i = 0; i < 4; i++)
#pragma unroll
            for (int j = 0; j < 4; j++) acc[i][j] = 0.0f;
        for (int k0 = 0; k0 < 128; k0 += 32) {
            __syncthreads();
            {
                int r = tid >> 3, c = (tid & 7) * 4;
                float4 v = make_float4(0.f, 0.f, 0.f, 0.f);
                if (row0 + r < G)
                    v = *(const float4*)&g_z1[(size_t)(row0 + r) * 128 + k0 + c];
                int cg = k0 + c;
                v.x = v.x * s_scale[cg]     + s_shift[cg];
                v.y = v.y * s_scale[cg + 1] + s_shift[cg + 1];
                v.z = v.z * s_scale[cg + 2] + s_shift[cg + 2];
                v.w = v.w * s_scale[cg + 3] + s_shift[cg + 3];
                v.x = v.x > 0.f ? v.x : SLOPE * v.x;
                v.y = v.y > 0.f ? v.y : SLOPE * v.y;
                v.z = v.z > 0.f ? v.z : SLOPE * v.z;
                v.w = v.w > 0.f ? v.w : SLOPE * v.w;
                As[r][c] = v.x; As[r][c + 1] = v.y; As[r][c + 2] = v.z; As[r][c + 3] = v.w;
            }
#pragma unroll
            for (int i = 0; i < 4; i++) {
                int idx = tid + i * 256;
                int r = idx >> 5, c = (idx & 31) * 4;
                float4 v = *(const float4*)&Wf2[(size_t)(k0 + r) * 128 + c];
                *(float4*)&Bs[r][c] = v;
            }
            __syncthreads();
#pragma unroll
            for (int k = 0; k < 32; k++) {
                float a[4];
#pragma unroll
                for (int i = 0; i < 4; i++) a[i] = As[ty * 4 + i][k];
                float4 b = *(const float4*)&Bs[k][tx * 4];
#pragma unroll
                for (int i = 0; i < 4; i++) {
                    acc[i][0] += a[i] * b.x;
                    acc[i][1] += a[i] * b.y;
                    acc[i][2] += a[i] * b.z;
                    acc[i][3] += a[i] * b.w;
                }
            }
        }
        float bx = bf2[tx * 4], by = bf2[tx * 4 + 1], bz = bf2[tx * 4 + 2], bw = bf2[tx * 4 + 3];
#pragma unroll
        for (int i = 0; i < 4; i++) {
            int r = row0 + ty * 4 + i;
            if (r < G) {
                float4 o;
                o.x = acc[i][0] + bx;
                o.y = acc[i][1] + by;
                o.z = acc[i][2] + bz;
                o.w = acc[i][3] + bw;
                *(float4*)&out[(size_t)r * 128 + tx * 4] = o;
            }
        }
    }
}

// ---------------- driver ---------------------------------------------------------
extern "C" void kernel_launch(void* const* d_in, const int* in_sizes, int n_in,
                              void* d_out, int out_size) {
    const float* x      = (const float*)d_in[0];
    const int*   ei     = (const int*)d_in[1];
    const int*   batch  = (const int*)d_in[2];
    const float* W1  = (const float*)d_in[4];
    const float* b1  = (const float*)d_in[5];
    const float* g1  = (const float*)d_in[6];
    const float* be1 = (const float*)d_in[7];
    const float* W2  = (const float*)d_in[8];
    const float* b2  = (const float*)d_in[9];
    const float* g2  = (const float*)d_in[10];
    const float* be2 = (const float*)d_in[11];
    const float* W3  = (const float*)d_in[12];
    const float* b3  = (const float*)d_in[13];
    const float* g3  = (const float*)d_in[14];
    const float* be3 = (const float*)d_in[15];
    const float* Wf1 = (const float*)d_in[16];
    const float* bf1 = (const float*)d_in[17];
    const float* g4  = (const float*)d_in[18];
    const float* be4 = (const float*)d_in[19];
    const float* Wf2 = (const float*)d_in[20];
    const float* bf2 = (const float*)d_in[21];

    int N = in_sizes[0] / D;
    int E = in_sizes[1] / 2;
    int G = out_size / D;
    if (N > NMAX || E > EMAX || G > GMAX) return;

    cudaFuncSetAttribute(k_gemm_bf16, cudaFuncAttributeMaxDynamicSharedMemorySize,
                         GEMM_U32 * 4);

    float *buf1, *buf2;
    float *csum, *csq;
    uint32_t *wbh, *wbl;
    cudaGetSymbolAddress((void**)&buf1, g_buf1);
    cudaGetSymbolAddress((void**)&buf2, g_buf2);
    cudaGetSymbolAddress((void**)&wbh, g_WBh);
    cudaGetSymbolAddress((void**)&wbl, g_WBl);
    cudaGetSymbolAddress((void**)&csum, g_colsum);
    cudaGetSymbolAddress((void**)&csq, g_colsq);

    int NC = (N + CH - 1) / CH;
    int mx = max(E, N);

    static cudaStream_t sB = nullptr;
    static cudaEvent_t evFork = nullptr, evCSR = nullptr;
    if (sB == nullptr) {
        cudaStreamCreateWithFlags(&sB, cudaStreamNonBlocking);
        cudaEventCreateWithFlags(&evFork, cudaEventDisableTiming);
        cudaEventCreateWithFlags(&evCSR, cudaEventDisableTiming);
    }

    cudaEventRecord(evFork, 0);
    cudaStreamWaitEvent(sB, evFork, 0);
    k_zero<<<(N + 255) / 256, 256, 0, sB>>>(N);
    k_count<<<(mx + 255) / 256, 256, 0, sB>>>(ei, batch, E, N);
    k_scan<<<NC, CH, 0, sB>>>(N, NC, G);
    k_scatter<<<(E + 255) / 256, 256, 0, sB>>>(ei, E);
    cudaEventRecord(evCSR, sB);

    const float* bs[3]  = {b1, b2, b3};
    const float* gs[3]  = {g1, g2, g3};
    const float* bes[3] = {be1, be2, be3};

    int tc_grid    = (N + 127) / 128;
    int agg_blocks = (N + 7) / 8;

    k_prep<<<dim3(4, 4, 3), dim3(32, 8)>>>(W1, W2, W3);
    k_gemm_bf16<<<tc_grid, 256, GEMM_U32 * 4>>>(x, wbh, wbl, buf1, N, 0,
                                                nullptr, nullptr, nullptr, nullptr, N);

    cudaStreamWaitEvent(0, evCSR, 0);

    for (int L = 0; L < 3; L++) {
        if (L > 0)
            k_gemm_bf16<<<tc_grid, 256, GEMM_U32 * 4>>>(
                buf2, wbh + L * D * 64, wbl + L * D * 64, buf1, N, 1,
                csum + (L - 1) * D * 32, csq + (L - 1) * D * 32, gs[L - 1], bes[L - 1], N);
        k_aggregate<<<agg_blocks, 256>>>(buf1, bs[L], buf2, N, L);
    }

    int tb = (G + 7) / 8;
    k_tail<<<tb, 256>>>(buf2, G, N, gs[2], bes[2], Wf1, bf1, g4, be4, Wf2, bf2,
                        (float*)d_out);
}

// round 16
// speedup vs baseline: 1.0047x; 1.0004x over previous
#include <cuda_runtime.h>
#include <cuda_bf16.h>
#include <math.h>
#include <stdint.h>

#define D 128
#define NMAX 50000
#define EMAX 800000
#define GMAX 512
#define BN_EPS 1e-5f
#define SLOPE 0.1f
#define CH 512
#define NCMAX 512

// ---------------- scratch (static device globals; zero-initialized) -----------
__device__ float    g_buf1[NMAX * D];
__device__ float    g_buf2[NMAX * D];
__device__ uint32_t g_WBh[3][D * 64];
__device__ uint32_t g_WBl[3][D * 64];
__device__ float    g_dinv[NMAX];
__device__ int      g_deg[NMAX];          // self-cleaned by k_scan
__device__ int      g_rowstart[NMAX + 1];
__device__ int      g_wpos[NMAX];
__device__ int2     g_edge[EMAX];
__device__ int      g_csum[NCMAX];
__device__ int      g_coff[NCMAX];
__device__ float    g_colsum[3][D * 32];  // zeroed by k_prep each call
__device__ float    g_colsq[3][D * 32];
__device__ float    g_tsum[D * 32];
__device__ float    g_tsq[D * 32];
__device__ int      g_gcnt[GMAX];         // self-cleaned by k_scan
__device__ int      g_gstart[GMAX + 1];
__device__ float    g_pooled[GMAX * D];
__device__ float    g_z1[GMAX * D];
__device__ int      g_scan_cnt = 0;       // self-reset
__device__ int      g_scan_flag = 0;      // self-reset
__device__ int      g_scan_done = 0;      // self-reset
__device__ int      g_tail_cnt = 0;       // self-reset
__device__ int      g_tail_done = 0;      // self-reset

// ---------------- helpers ------------------------------------------------------
__device__ __forceinline__ uint32_t smem_u32(const void* p) {
    uint32_t a;
    asm("{ .reg .u64 t; cvta.to.shared.u64 t, %1; cvt.u32.u64 %0, t; }" : "=r"(a) : "l"(p));
    return a;
}
__device__ __forceinline__ void ldsm_x4(uint32_t& r0, uint32_t& r1, uint32_t& r2,
                                        uint32_t& r3, uint32_t addr) {
    asm volatile("ldmatrix.sync.aligned.m8n8.x4.shared.b16 {%0,%1,%2,%3}, [%4];"
                 : "=r"(r0), "=r"(r1), "=r"(r2), "=r"(r3) : "r"(addr));
}
__device__ __forceinline__ void bf16_split_pack(float v0, float v1,
                                                uint32_t& h, uint32_t& l) {
    __nv_bfloat16 h0 = __float2bfloat16_rn(v0);
    __nv_bfloat16 h1 = __float2bfloat16_rn(v1);
    float r0 = v0 - __bfloat162float(h0);
    float r1 = v1 - __bfloat162float(h1);
    __nv_bfloat16 l0 = __float2bfloat16_rn(r0);
    __nv_bfloat16 l1 = __float2bfloat16_rn(r1);
    h = ((uint32_t)__bfloat16_as_ushort(h1) << 16) | __bfloat16_as_ushort(h0);
    l = ((uint32_t)__bfloat16_as_ushort(l1) << 16) | __bfloat16_as_ushort(l0);
}
__device__ __forceinline__ void mma_bf16(float* d, const uint32_t* a, const uint32_t* b) {
    asm volatile(
        "mma.sync.aligned.m16n8k16.row.col.f32.bf16.bf16.f32 "
        "{%0,%1,%2,%3}, {%4,%5,%6,%7}, {%8,%9}, {%0,%1,%2,%3};"
        : "+f"(d[0]), "+f"(d[1]), "+f"(d[2]), "+f"(d[3])
        : "r"(a[0]), "r"(a[1]), "r"(a[2]), "r"(a[3]), "r"(b[0]), "r"(b[1]));
}

// ---------------- bf16 3-term split GEMM (ldmatrix fragments) -----------------
#define ASTU 36
#define BSTU 68
#define SA_H 0
#define SA_L (128 * ASTU)
#define SB_H (2 * 128 * ASTU)
#define SB_L (SB_H + 128 * BSTU)
#define GEMM_U32 (SB_H + 2 * 128 * BSTU)

__global__ void __launch_bounds__(256, 2)
k_gemm_bf16(const float* __restrict__ A, const uint32_t* __restrict__ Bh,
            const uint32_t* __restrict__ Bl, float* __restrict__ C,
            int M, int apply_norm,
            const float* __restrict__ csum, const float* __restrict__ csq,
            const float* __restrict__ gamma, const float* __restrict__ beta,
            int Nn) {
    extern __shared__ uint32_t su[];
    __shared__ float s_scale[D];
    __shared__ float s_shift[D];
    uint32_t* sAh = su + SA_H;
    uint32_t* sAl = su + SA_L;
    uint32_t* sBh = su + SB_H;
    uint32_t* sBl = su + SB_L;

    const int tid = threadIdx.x;
    const int wid = tid >> 5;
    const int lid = tid & 31;
    const int wm  = wid & 1;
    const int wn  = wid >> 1;
    const int row0 = blockIdx.x * 128;

    const uint32_t su_a = smem_u32(su);
    const uint32_t sAh_a = su_a + SA_H * 4;
    const uint32_t sAl_a = su_a + SA_L * 4;
    const uint32_t sBh_a = su_a + SB_H * 4;
    const uint32_t sBl_a = su_a + SB_L * 4;

    const int arow  = lid & 15;
    const int akoff = (lid & 16) ? 4 : 0;
    uint32_t aoff[4];
#pragma unroll
    for (int mt = 0; mt < 4; mt++)
        aoff[mt] = (uint32_t)(((wm * 64 + mt * 16 + arow) * ASTU + akoff) * 4);
    const int brow  = wn * 32 + (lid & 7) + ((lid & 16) ? 8 : 0);
    const int bkoff = (lid & 8) ? 4 : 0;
    uint32_t boff[2];
#pragma unroll
    for (int q = 0; q < 2; q++)
        boff[q] = (uint32_t)(((brow + q * 16) * BSTU + bkoff) * 4);

    if (apply_norm && tid < D) {
        float ts = csum[tid * 32];
        float tq = csq[tid * 32];
        float mu = ts / (float)Nn;
        float var = tq / (float)Nn - mu * mu;
        float rinv = rsqrtf(var + BN_EPS);
        float sc = rinv * gamma[tid];
        s_scale[tid] = sc;
        s_shift[tid] = beta[tid] - mu * sc;
    }

#pragma unroll
    for (int i = 0; i < 8; i++) {
        int idx = tid + i * 256;
        int r = idx >> 4;
        int q = (idx & 15) * 4;
        *(uint4*)&sBh[r * BSTU + q] = *(const uint4*)&Bh[r * 64 + q];
        *(uint4*)&sBl[r * BSTU + q] = *(const uint4*)&Bl[r * 64 + q];
    }
    if (apply_norm) __syncthreads();

    float acc[4][4][4];
#pragma unroll
    for (int mt = 0; mt < 4; mt++)
#pragma unroll
        for (int nt = 0; nt < 4; nt++)
#pragma unroll
            for (int i = 0; i < 4; i++) acc[mt][nt][i] = 0.0f;

    for (int p = 0; p < 2; p++) {
        if (p) __syncthreads();
#pragma unroll
        for (int i = 0; i < 8; i++) {
            int idx = tid + i * 256;
            int r = idx >> 4;
            int c4 = (idx & 15) * 4;
            float4 v = make_float4(0.f, 0.f, 0.f, 0.f);
            if (row0 + r < M)
                v = *(const float4*)&A[(size_t)(row0 + r) * 128 + p * 64 + c4];
            if (apply_norm) {
                int cg = p * 64 + c4;
                v.x = v.x * s_scale[cg]     + s_shift[cg];
                v.y = v.y * s_scale[cg + 1] + s_shift[cg + 1];
                v.z = v.z * s_scale[cg + 2] + s_shift[cg + 2];
                v.w = v.w * s_scale[cg + 3] + s_shift[cg + 3];
                v.x = v.x > 0.f ? v.x : SLOPE * v.x;
                v.y = v.y > 0.f ? v.y : SLOPE * v.y;
                v.z = v.z > 0.f ? v.z : SLOPE * v.z;
                v.w = v.w > 0.f ? v.w : SLOPE * v.w;
            }
            uint2 hp, lp;
            bf16_split_pack(v.x, v.y, hp.x, lp.x);
            bf16_split_pack(v.z, v.w, hp.y, lp.y);
            *(uint2*)&sAh[r * ASTU + (c4 >> 1)] = hp;
            *(uint2*)&sAl[r * ASTU + (c4 >> 1)] = lp;
        }
        __syncthreads();

        const uint32_t pB = (uint32_t)(p * 32 * 4);
#pragma unroll
        for (int k16 = 0; k16 < 4; k16++) {
            const uint32_t kb4 = (uint32_t)(k16 * 8 * 4);
            uint32_t af[4][4], bh[4][2], bl[4][2];
#pragma unroll
            for (int mt = 0; mt < 4; mt++)
                ldsm_x4(af[mt][0], af[mt][1], af[mt][2], af[mt][3],
                        sAh_a + aoff[mt] + kb4);
            ldsm_x4(bh[0][0], bh[0][1], bh[1][0], bh[1][1], sBh_a + boff[0] + pB + kb4);
            ldsm_x4(bh[2][0], bh[2][1], bh[3][0], bh[3][1], sBh_a + boff[1] + pB + kb4);
            ldsm_x4(bl[0][0], bl[0][1], bl[1][0], bl[1][1], sBl_a + boff[0] + pB + kb4);
            ldsm_x4(bl[2][0], bl[2][1], bl[3][0], bl[3][1], sBl_a + boff[1] + pB + kb4);
#pragma unroll
            for (int mt = 0; mt < 4; mt++)
#pragma unroll
                for (int nt = 0; nt < 4; nt++)
                    mma_bf16(acc[mt][nt], af[mt], bh[nt]);
#pragma unroll
            for (int mt = 0; mt < 4; mt++)
#pragma unroll
                for (int nt = 0; nt < 4; nt++)
                    mma_bf16(acc[mt][nt], af[mt], bl[nt]);
#pragma unroll
            for (int mt = 0; mt < 4; mt++)
                ldsm_x4(af[mt][0], af[mt][1], af[mt][2], af[mt][3],
                        sAl_a + aoff[mt] + kb4);
#pragma unroll
            for (int mt = 0; mt < 4; mt++)
#pragma unroll
                for (int nt = 0; nt < 4; nt++)
                    mma_bf16(acc[mt][nt], af[mt], bh[nt]);
        }
    }
    __syncthreads();

    const int g  = lid >> 2;
    const int tg = lid & 3;
    float* sOut = (float*)su;
#pragma unroll
    for (int mt = 0; mt < 4; mt++) {
        int r0 = wm * 64 + mt * 16 + g;
#pragma unroll
        for (int nt = 0; nt < 4; nt++) {
            int c0 = wn * 32 + nt * 8 + tg * 2;
            sOut[r0 * 129 + c0]           = acc[mt][nt][0];
            sOut[r0 * 129 + c0 + 1]       = acc[mt][nt][1];
            sOut[(r0 + 8) * 129 + c0]     = acc[mt][nt][2];
            sOut[(r0 + 8) * 129 + c0 + 1] = acc[mt][nt][3];
        }
    }
    __syncthreads();

#pragma unroll 4
    for (int i = 0; i < 64; i++) {
        int idx = tid + i * 256;
        int r = idx >> 7;
        int c = idx & 127;
        if (row0 + r < M)
            C[(size_t)(row0 + r) * 128 + c] = sOut[r * 129 + c];
    }
}

// ---------------- weight prep + accumulator zeroing ---------------------------
__global__ void k_prep(const float* __restrict__ W1, const float* __restrict__ W2,
                       const float* __restrict__ W3) {
    __shared__ float s[32][33];
    const float* W = (blockIdx.z == 0) ? W1 : (blockIdx.z == 1) ? W2 : W3;
    uint32_t* Oh = g_WBh[blockIdx.z];
    uint32_t* Ol = g_WBl[blockIdx.z];
    int bx = blockIdx.x, by = blockIdx.y;
    int tx = threadIdx.x, ty = threadIdx.y;

    int bid = blockIdx.z * 16 + blockIdx.y * 4 + blockIdx.x;
    int gi = bid * 256 + ty * 32 + tx;
    g_colsum[0][gi] = 0.f;
    g_colsq[0][gi] = 0.f;
    if (gi < D * 32) { g_tsum[gi] = 0.f; g_tsq[gi] = 0.f; }

#pragma unroll
    for (int i = 0; i < 32; i += 8)
        s[ty + i][tx] = W[(by * 32 + ty + i) * 128 + bx * 32 + tx];
    __syncthreads();
#pragma unroll
    for (int p = ty; p < 16; p += 8) {
        float v0 = s[2 * p][tx];
        float v1 = s[2 * p + 1][tx];
        uint32_t h, l;
        bf16_split_pack(v0, v1, h, l);
        int o = (bx * 32 + tx) * 64 + by * 16 + p;
        Oh[o] = h;
        Ol[o] = l;
    }
}

// ---------------- count (deg/gcnt zeroed by previous k_scan or static init) ---
__global__ void k_count(const int* __restrict__ ei, const int* __restrict__ batch,
                        int E, int N) {
    int i = blockIdx.x * blockDim.x + threadIdx.x;
    if (i < E) atomicAdd(&g_deg[ei[E + i]], 1);
    if (i < N) atomicAdd(&g_gcnt[batch[i]], 1);
}

// ---------------- single fused self-cleaning scan ------------------------------
__global__ void k_scan(int N, int NC, int G) {
    __shared__ int s[CH];
    __shared__ int ticket;
    int t = threadIdx.x;
    int i = blockIdx.x * CH + t;
    int v = (i < N) ? g_deg[i] : 0;
    s[t] = v;
    __syncthreads();
    for (int off = 1; off < CH; off <<= 1) {
        int x = (t >= off) ? s[t - off] : 0;
        __syncthreads();
        s[t] += x;
        __syncthreads();
    }
    int local = s[t];
    int btotal = s[CH - 1];
    if (t == 0) {
        g_csum[blockIdx.x] = btotal;
        __threadfence();
        ticket = atomicAdd(&g_scan_cnt, 1);
    }
    __syncthreads();
    if (ticket == gridDim.x - 1) {
        int cv = (t < NC) ? g_csum[t] : 0;
        s[t] = cv;
        __syncthreads();
        for (int off = 1; off < CH; off <<= 1) {
            int x = (t >= off) ? s[t - off] : 0;
            __syncthreads();
            s[t] += x;
            __syncthreads();
        }
        if (t < NC) g_coff[t] = s[t] - cv;
        if (t == NC - 1) g_rowstart[N] = s[t];
        __syncthreads();
        int gc = (t < G) ? g_gcnt[t] : 0;
        s[t] = gc;
        __syncthreads();
        for (int off = 1; off < CH; off <<= 1) {
            int x = (t >= off) ? s[t - off] : 0;
            __syncthreads();
            s[t] += x;
            __syncthreads();
        }
        if (t < G) { g_gstart[t] = s[t] - gc; g_gcnt[t] = 0; }
        if (t == G - 1) g_gstart[G] = s[t];
        if (t == 0) g_scan_cnt = 0;           // all increments already landed
        __threadfence();
        if (t == 0) atomicExch(&g_scan_flag, 1);
    } else {
        if (t == 0) {
            while (atomicAdd(&g_scan_flag, 0) == 0) __nanosleep(64);
        }
        __syncthreads();
    }
    int co = *((volatile int*)&g_coff[blockIdx.x]);
    if (i < N) {
        int excl = co + local - v;
        g_rowstart[i] = excl;
        g_wpos[i] = excl;
        g_dinv[i] = rsqrtf((float)v + 1.0f);
        g_deg[i] = 0;                          // self-clean for next replay
    }
    // reset flag once ALL blocks have passed the spin
    __syncthreads();
    if (t == 0) {
        int d = atomicAdd(&g_scan_done, 1);
        if (d == gridDim.x - 1) {
            g_scan_done = 0;
            atomicExch(&g_scan_flag, 0);
        }
    }
}

// ---------------- scatter: packed 8-byte payload ------------------------------
__global__ void k_scatter(const int* __restrict__ ei, int E) {
    int e = blockIdx.x * blockDim.x + threadIdx.x;
    if (e < E) {
        int s = ei[e];
        int d = ei[E + e];
        int p = atomicAdd(&g_wpos[d], 1);
        int2 pk;
        pk.x = s;
        pk.y = __float_as_int(g_dinv[s] * g_dinv[d]);
        g_edge[p] = pk;
    }
}

// ---------------- edge aggregation + fused stats partials -----------------------
__global__ void k_aggregate(const float* __restrict__ h, const float* __restrict__ bias,
                            float* __restrict__ agg, int N, int layer) {
    __shared__ float s_sum[8][132];
    __shared__ float s_sq[8][132];
    const int wid = threadIdx.x >> 5;
    const int lane = threadIdx.x & 31;
    const int node = blockIdx.x * 8 + wid;
    const float4* __restrict__ h4 = (const float4*)h;

    float4 acc0 = make_float4(0.f, 0.f, 0.f, 0.f);
    if (node < N) {
        float di = g_dinv[node];
        float sc = di * di;
        float4 a = h4[(size_t)node * 32 + lane];
        acc0.x = a.x * sc; acc0.y = a.y * sc; acc0.z = a.z * sc; acc0.w = a.w * sc;
        float4 acc1 = make_float4(0.f, 0.f, 0.f, 0.f);
        float4 acc2 = make_float4(0.f, 0.f, 0.f, 0.f);
        float4 acc3 = make_float4(0.f, 0.f, 0.f, 0.f);

        int j = g_rowstart[node];
        int s1 = g_rowstart[node + 1];
        for (; j + 4 <= s1; j += 4) {
            int2 e0 = g_edge[j];
            int2 e1 = g_edge[j + 1];
            int2 e2 = g_edge[j + 2];
            int2 e3 = g_edge[j + 3];
            float4 v0 = h4[(size_t)e0.x * 32 + lane];
            float4 v1 = h4[(size_t)e1.x * 32 + lane];
            float4 v2 = h4[(size_t)e2.x * 32 + lane];
            float4 v3 = h4[(size_t)e3.x * 32 + lane];
            float c0 = __int_as_float(e0.y);
            float c1 = __int_as_float(e1.y);
            float c2 = __int_as_float(e2.y);
            float c3 = __int_as_float(e3.y);
            acc0.x += v0.x * c0; acc0.y += v0.y * c0; acc0.z += v0.z * c0; acc0.w += v0.w * c0;
            acc1.x += v1.x * c1; acc1.y += v1.y * c1; acc1.z += v1.z * c1; acc1.w += v1.w * c1;
            acc2.x += v2.x * c2; acc2.y += v2.y * c2; acc2.z += v2.z * c2; acc2.w += v2.w * c2;
            acc3.x += v3.x * c3; acc3.y += v3.y * c3; acc3.z += v3.z * c3; acc3.w += v3.w * c3;
        }
        for (; j < s1; j++) {
            int2 e0 = g_edge[j];
            float c = __int_as_float(e0.y);
            float4 v = h4[(size_t)e0.x * 32 + lane];
            acc0.x += v.x * c; acc0.y += v.y * c; acc0.z += v.z * c; acc0.w += v.w * c;
        }
        float4 b = ((const float4*)bias)[lane];
        acc0.x += acc1.x + acc2.x + acc3.x + b.x;
        acc0.y += acc1.y + acc2.y + acc3.y + b.y;
        acc0.z += acc1.z + acc2.z + acc3.z + b.z;
        acc0.w += acc1.w + acc2.w + acc3.w + b.w;
        ((float4*)agg)[(size_t)node * 32 + lane] = acc0;
    }

    int c4 = lane * 4;
    s_sum[wid][c4]     = acc0.x;
    s_sum[wid][c4 + 1] = acc0.y;
    s_sum[wid][c4 + 2] = acc0.z;
    s_sum[wid][c4 + 3] = acc0.w;
    s_sq[wid][c4]      = acc0.x * acc0.x;
    s_sq[wid][c4 + 1]  = acc0.y * acc0.y;
    s_sq[wid][c4 + 2]  = acc0.z * acc0.z;
    s_sq[wid][c4 + 3]  = acc0.w * acc0.w;
    __syncthreads();

    int c = threadIdx.x;
    if (c < D) {
        float ts = 0.f, tq = 0.f;
#pragma unroll
        for (int w = 0; w < 8; w++) { ts += s_sum[w][c]; tq += s_sq[w][c]; }
        atomicAdd(&g_colsum[layer][c * 32], ts);
        atomicAdd(&g_colsq[layer][c * 32], tq);
    }
}

// ---------------- fused tail: pool + FC1(+stats) + FC2 --------------------------
__device__ __forceinline__ void tail_barrier(int target) {
    __threadfence();
    __syncthreads();
    if (threadIdx.x == 0) {
        atomicAdd(&g_tail_cnt, 1);
        while (atomicAdd(&g_tail_cnt, 0) < target) __nanosleep(64);
    }
    __syncthreads();
}

__global__ void k_tail(const float* __restrict__ h, int G, int N,
                       const float* __restrict__ gamma2, const float* __restrict__ beta2,
                       const float* __restrict__ Wf1, const float* __restrict__ bf1,
                       const float* __restrict__ g4, const float* __restrict__ be4,
                       const float* __restrict__ Wf2, const float* __restrict__ bf2,
                       float* __restrict__ out) {
    __shared__ float s_scale[D], s_shift[D];
    __shared__ float As[32][36];
    __shared__ float Bs[32][132];
    __shared__ float s_sum[8][132], s_sq[8][132];
    const int tid = threadIdx.x;
    const int tx = tid & 31;
    const int ty = tid >> 5;
    const int nb = gridDim.x;
    const int row0 = blockIdx.x * 32;

    if (tid < D) {
        float ts = g_colsum[2][tid * 32];
        float tq = g_colsq[2][tid * 32];
        float mu = ts / (float)N;
        float var = tq / (float)N - mu * mu;
        float rinv = rsqrtf(var + BN_EPS);
        float sc = rinv * gamma2[tid];
        s_scale[tid] = sc;
        s_shift[tid] = beta2[tid] - mu * sc;
    }
    __syncthreads();
    {
        int warp = blockIdx.x * 8 + ty;
        if (warp < G) {
            const float4* h4 = (const float4*)h;
            int c = tx * 4;
            float4 sc4 = *(float4*)&s_scale[c];
            float4 sh4 = *(float4*)&s_shift[c];
            int s0 = g_gstart[warp], s1 = g_gstart[warp + 1];
            float4 acc = make_float4(0.f, 0.f, 0.f, 0.f);
            for (int r = s0; r < s1; r++) {
                float4 v = h4[(size_t)r * 32 + tx];
                float ax = v.x * sc4.x + sh4.x;
                float ay = v.y * sc4.y + sh4.y;
                float az = v.z * sc4.z + sh4.z;
                float aw = v.w * sc4.w + sh4.w;
                acc.x += ax > 0.f ? ax : SLOPE * ax;
                acc.y += ay > 0.f ? ay : SLOPE * ay;
                acc.z += az > 0.f ? az : SLOPE * az;
                acc.w += aw > 0.f ? aw : SLOPE * aw;
            }
            int cnt = s1 - s0;
            float inv = 1.0f / (float)(cnt > 0 ? cnt : 1);
            acc.x *= inv; acc.y *= inv; acc.z *= inv; acc.w *= inv;
            ((float4*)g_pooled)[(size_t)warp * 32 + tx] = acc;
        }
    }
    tail_barrier(nb);

    if (row0 < G) {
        float acc[4][4];
#pragma unroll
        for (int i = 0; i < 4; i++)
#pragma unroll
            for (int j = 0; j < 4; j++) acc[i][j] = 0.0f;
        for (int k0 = 0; k0 < 128; k0 += 32) {
            __syncthreads();
            {
                int r = tid >> 3, c = (tid & 7) * 4;
                float4 v = make_float4(0.f, 0.f, 0.f, 0.f);
                if (row0 + r < G)
                    v = *(const float4*)&g_pooled[(size_t)(row0 + r) * 128 + k0 + c];
                As[r][c] = v.x; As[r][c + 1] = v.y; As[r][c + 2] = v.z; As[r][c + 3] = v.w;
            }
#pragma unroll
            for (int i = 0; i < 4; i++) {
                int idx = tid + i * 256;
                int r = idx >> 5, c = (idx & 31) * 4;
                float4 v = *(const float4*)&Wf1[(size_t)(k0 + r) * 128 + c];
                *(float4*)&Bs[r][c] = v;
            }
            __syncthreads();
#pragma unroll
            for (int k = 0; k < 32; k++) {
                float a[4];
#pragma unroll
                for (int i = 0; i < 4; i++) a[i] = As[ty * 4 + i][k];
                float4 b = *(const float4*)&Bs[k][tx * 4];
#pragma unroll
                for (int i = 0; i < 4; i++) {
                    acc[i][0] += a[i] * b.x;
                    acc[i][1] += a[i] * b.y;
                    acc[i][2] += a[i] * b.z;
                    acc[i][3] += a[i] * b.w;
                }
            }
        }
        float bx = bf1[tx * 4], by = bf1[tx * 4 + 1], bz = bf1[tx * 4 + 2], bw = bf1[tx * 4 + 3];
        float cs[4] = {0.f, 0.f, 0.f, 0.f};
        float cq[4] = {0.f, 0.f, 0.f, 0.f};
#pragma unroll
        for (int i = 0; i < 4; i++) {
            int r = row0 + ty * 4 + i;
            if (r < G) {
                float4 o;
                o.x = acc[i][0] + bx;
                o.y = acc[i][1] + by;
                o.z = acc[i][2] + bz;
                o.w = acc[i][3] + bw;
                *(float4*)&g_z1[(size_t)r * 128 + tx * 4] = o;
                cs[0] += o.x; cs[1] += o.y; cs[2] += o.z; cs[3] += o.w;
                cq[0] += o.x * o.x; cq[1] += o.y * o.y; cq[2] += o.z * o.z; cq[3] += o.w * o.w;
            }
        }
        __syncthreads();
#pragma unroll
        for (int j = 0; j < 4; j++) {
            s_sum[ty][tx * 4 + j] = cs[j];
            s_sq[ty][tx * 4 + j]  = cq[j];
        }
        __syncthreads();
        if (tid < D) {
            float ts = 0.f, tq = 0.f;
#pragma unroll
            for (int w = 0; w < 8; w++) { ts += s_sum[w][tid]; tq += s_sq[w][tid]; }
            atomicAdd(&g_tsum[tid * 32], ts);
            atomicAdd(&g_tsq[tid * 32], tq);
        }
    }
    tail_barrier(2 * nb);

    if (row0 < G) {
        if (tid < D) {
            float ts = g_tsum[tid * 32];
            float tq = g_tsq[tid * 32];
            float mu = ts / (float)G;
            float var = tq / (float)G - mu * mu;
            float rinv = rsqrtf(var + BN_EPS);
            float sc = rinv * g4[tid];
            s_scale[tid] = sc;
            s_shift[tid] = be4[tid] - mu * sc;
        }
        float acc[4][4];
#pragma unroll
        for (int i = 0; i < 4; i++)
#pragma unroll
            for (int j = 0; j < 4; j++) acc[i][j] = 0.0f;
        for (int k0 = 0; k0 < 128; k0 += 32) {
            __syncthreads();
            {
                int r = tid >> 3, c = (tid & 7) * 4;
                float4 v = make_float4(0.f, 0.f, 0.f, 0.f);
                if (row0 + r < G)
                    v = *(const float4*)&g_z1[(size_t)(row0 + r) * 128 + k0 + c];
                int cg = k0 + c;
                v.x = v.x * s_scale[cg]     + s_shift[cg];
                v.y = v.y * s_scale[cg + 1] + s_shift[cg + 1];
                v.z = v.z * s_scale[cg + 2] + s_shift[cg + 2];
                v.w = v.w * s_scale[cg + 3] + s_shift[cg + 3];
                v.x = v.x > 0.f ? v.x : SLOPE * v.x;
                v.y = v.y > 0.f ? v.y : SLOPE * v.y;
                v.z = v.z > 0.f ? v.z : SLOPE * v.z;
                v.w = v.w > 0.f ? v.w : SLOPE * v.w;
                As[r][c] = v.x; As[r][c + 1] = v.y; As[r][c + 2] = v.z; As[r][c + 3] = v.w;
            }
#pragma unroll
            for (int i = 0; i < 4; i++) {
                int idx = tid + i * 256;
                int r = idx >> 5, c = (idx & 31) * 4;
                float4 v = *(const float4*)&Wf2[(size_t)(k0 + r) * 128 + c];
                *(float4*)&Bs[r][c] = v;
            }
            __syncthreads();
#pragma unroll
            for (int k = 0; k < 32; k++) {
                float a[4];
#pragma unroll
                for (int i = 0; i < 4; i++) a[i] = As[ty * 4 + i][k];
                float4 b = *(const float4*)&Bs[k][tx * 4];
#pragma unroll
                for (int i = 0; i < 4; i++) {
                    acc[i][0] += a[i] * b.x;
                    acc[i][1] += a[i] * b.y;
                    acc[i][2] += a[i] * b.z;
                    acc[i][3] += a[i] * b.w;
                }
            }
        }
        float bx = bf2[tx * 4], by = bf2[tx * 4 + 1], bz = bf2[tx * 4 + 2], bw = bf2[tx * 4 + 3];
#pragma unroll
        for (int i = 0; i < 4; i++) {
            int r = row0 + ty * 4 + i;
            if (r < G) {
                float4 o;
                o.x = acc[i][0] + bx;
                o.y = acc[i][1] + by;
                o.z = acc[i][2] + bz;
                o.w = acc[i][3] + bw;
                *(float4*)&out[(size_t)r * 128 + tx * 4] = o;
            }
        }
    }

    // self-reset tail counter after everyone has passed the last barrier
    __syncthreads();
    if (tid == 0) {
        int d = atomicAdd(&g_tail_done, 1);
        if (d == nb - 1) {
            g_tail_done = 0;
            atomicExch(&g_tail_cnt, 0);
        }
    }
}

// ---------------- driver ---------------------------------------------------------
extern "C" void kernel_launch(void* const* d_in, const int* in_sizes, int n_in,
                              void* d_out, int out_size) {
    const float* x      = (const float*)d_in[0];
    const int*   ei     = (const int*)d_in[1];
    const int*   batch  = (const int*)d_in[2];
    const float* W1  = (const float*)d_in[4];
    const float* b1  = (const float*)d_in[5];
    const float* g1  = (const float*)d_in[6];
    const float* be1 = (const float*)d_in[7];
    const float* W2  = (const float*)d_in[8];
    const float* b2  = (const float*)d_in[9];
    const float* g2  = (const float*)d_in[10];
    const float* be2 = (const float*)d_in[11];
    const float* W3  = (const float*)d_in[12];
    const float* b3  = (const float*)d_in[13];
    const float* g3  = (const float*)d_in[14];
    const float* be3 = (const float*)d_in[15];
    const float* Wf1 = (const float*)d_in[16];
    const float* bf1 = (const float*)d_in[17];
    const float* g4  = (const float*)d_in[18];
    const float* be4 = (const float*)d_in[19];
    const float* Wf2 = (const float*)d_in[20];
    const float* bf2 = (const float*)d_in[21];

    int N = in_sizes[0] / D;
    int E = in_sizes[1] / 2;
    int G = out_size / D;
    if (N > NMAX || E > EMAX || G > GMAX) return;

    cudaFuncSetAttribute(k_gemm_bf16, cudaFuncAttributeMaxDynamicSharedMemorySize,
                         GEMM_U32 * 4);

    float *buf1, *buf2;
    float *csum, *csq;
    uint32_t *wbh, *wbl;
    cudaGetSymbolAddress((void**)&buf1, g_buf1);
    cudaGetSymbolAddress((void**)&buf2, g_buf2);
    cudaGetSymbolAddress((void**)&wbh, g_WBh);
    cudaGetSymbolAddress((void**)&wbl, g_WBl);
    cudaGetSymbolAddress((void**)&csum, g_colsum);
    cudaGetSymbolAddress((void**)&csq, g_colsq);

    int NC = (N + CH - 1) / CH;
    int mx = max(E, N);

    static cudaStream_t sB = nullptr;
    static cudaEvent_t evFork = nullptr, evCSR = nullptr;
    if (sB == nullptr) {
        cudaStreamCreateWithFlags(&sB, cudaStreamNonBlocking);
        cudaEventCreateWithFlags(&evFork, cudaEventDisableTiming);
        cudaEventCreateWithFlags(&evCSR, cudaEventDisableTiming);
    }

    cudaEventRecord(evFork, 0);
    cudaStreamWaitEvent(sB, evFork, 0);
    k_count<<<(mx + 255) / 256, 256, 0, sB>>>(ei, batch, E, N);
    k_scan<<<NC, CH, 0, sB>>>(N, NC, G);
    k_scatter<<<(E + 255) / 256, 256, 0, sB>>>(ei, E);
    cudaEventRecord(evCSR, sB);

    const float* bs[3]  = {b1, b2, b3};
    const float* gs[3]  = {g1, g2, g3};
    const float* bes[3] = {be1, be2, be3};

    int tc_grid    = (N + 127) / 128;
    int agg_blocks = (N + 7) / 8;

    k_prep<<<dim3(4, 4, 3), dim3(32, 8)>>>(W1, W2, W3);
    k_gemm_bf16<<<tc_grid, 256, GEMM_U32 * 4>>>(x, wbh, wbl, buf1, N, 0,
                                                nullptr, nullptr, nullptr, nullptr, N);

    cudaStreamWaitEvent(0, evCSR, 0);

    for (int L = 0; L < 3; L++) {
        if (L > 0)
            k_gemm_bf16<<<tc_grid, 256, GEMM_U32 * 4>>>(
                buf2, wbh + L * D * 64, wbl + L * D * 64, buf1, N, 1,
                csum + (L - 1) * D * 32, csq + (L - 1) * D * 32, gs[L - 1], bes[L - 1], N);
        k_aggregate<<<agg_blocks, 256>>>(buf1, bs[L], buf2, N, L);
    }

    int tb = (G + 7) / 8;
    k_tail<<<tb, 256>>>(buf2, G, N, gs[2], bes[2], Wf1, bf1, g4, be4, Wf2, bf2,
                        (float*)d_out);
}

// round 17
// speedup vs baseline: 1.0088x; 1.0041x over previous
#include <cuda_runtime.h>
#include <cuda_bf16.h>
#include <math.h>
#include <stdint.h>

#define D 128
#define NMAX 50000
#define EMAX 800000
#define GMAX 512
#define BN_EPS 1e-5f
#define SLOPE 0.1f
#define CH 512
#define NCMAX 512

#define PDL_WAIT()    asm volatile("griddepcontrol.wait;" ::: "memory")
#define PDL_TRIGGER() asm volatile("griddepcontrol.launch_dependents;" ::: "memory")

// ---------------- scratch (static device globals; zero-initialized) -----------
__device__ float    g_buf1[NMAX * D];
__device__ float    g_buf2[NMAX * D];
__device__ uint32_t g_WBh[3][D * 64];
__device__ uint32_t g_WBl[3][D * 64];
__device__ float    g_dinv[NMAX];
__device__ int      g_deg[NMAX];          // self-cleaned by k_scan
__device__ int      g_rowstart[NMAX + 1];
__device__ int      g_wpos[NMAX];
__device__ int2     g_edge[EMAX];
__device__ int      g_csum[NCMAX];
__device__ int      g_coff[NCMAX];
__device__ float    g_colsum[3][D * 32];  // zeroed by k_prep each call
__device__ float    g_colsq[3][D * 32];
__device__ float    g_tsum[D * 32];
__device__ float    g_tsq[D * 32];
__device__ int      g_gcnt[GMAX];         // self-cleaned by k_scan
__device__ int      g_gstart[GMAX + 1];
__device__ float    g_pooled[GMAX * D];
__device__ float    g_z1[GMAX * D];
__device__ int      g_scan_cnt = 0;
__device__ int      g_scan_flag = 0;
__device__ int      g_scan_done = 0;
__device__ int      g_tail_cnt = 0;
__device__ int      g_tail_done = 0;

// ---------------- helpers ------------------------------------------------------
__device__ __forceinline__ uint32_t smem_u32(const void* p) {
    uint32_t a;
    asm("{ .reg .u64 t; cvta.to.shared.u64 t, %1; cvt.u32.u64 %0, t; }" : "=r"(a) : "l"(p));
    return a;
}
__device__ __forceinline__ void ldsm_x4(uint32_t& r0, uint32_t& r1, uint32_t& r2,
                                        uint32_t& r3, uint32_t addr) {
    asm volatile("ldmatrix.sync.aligned.m8n8.x4.shared.b16 {%0,%1,%2,%3}, [%4];"
                 : "=r"(r0), "=r"(r1), "=r"(r2), "=r"(r3) : "r"(addr));
}
__device__ __forceinline__ void bf16_split_pack(float v0, float v1,
                                                uint32_t& h, uint32_t& l) {
    __nv_bfloat16 h0 = __float2bfloat16_rn(v0);
    __nv_bfloat16 h1 = __float2bfloat16_rn(v1);
    float r0 = v0 - __bfloat162float(h0);
    float r1 = v1 - __bfloat162float(h1);
    __nv_bfloat16 l0 = __float2bfloat16_rn(r0);
    __nv_bfloat16 l1 = __float2bfloat16_rn(r1);
    h = ((uint32_t)__bfloat16_as_ushort(h1) << 16) | __bfloat16_as_ushort(h0);
    l = ((uint32_t)__bfloat16_as_ushort(l1) << 16) | __bfloat16_as_ushort(l0);
}
__device__ __forceinline__ void mma_bf16(float* d, const uint32_t* a, const uint32_t* b) {
    asm volatile(
        "mma.sync.aligned.m16n8k16.row.col.f32.bf16.bf16.f32 "
        "{%0,%1,%2,%3}, {%4,%5,%6,%7}, {%8,%9}, {%0,%1,%2,%3};"
        : "+f"(d[0]), "+f"(d[1]), "+f"(d[2]), "+f"(d[3])
        : "r"(a[0]), "r"(a[1]), "r"(a[2]), "r"(a[3]), "r"(b[0]), "r"(b[1]));
}

// ---------------- bf16 3-term split GEMM (ldmatrix fragments, PDL) ------------
#define ASTU 36
#define BSTU 68
#define SA_H 0
#define SA_L (128 * ASTU)
#define SB_H (2 * 128 * ASTU)
#define SB_L (SB_H + 128 * BSTU)
#define GEMM_U32 (SB_H + 2 * 128 * BSTU)

__global__ void __launch_bounds__(256, 2)
k_gemm_bf16(const float* __restrict__ A, const uint32_t* __restrict__ Bh,
            const uint32_t* __restrict__ Bl, float* __restrict__ C,
            int M, int apply_norm,
            const float* __restrict__ csum, const float* __restrict__ csq,
            const float* __restrict__ gamma, const float* __restrict__ beta,
            int Nn) {
    extern __shared__ uint32_t su[];
    __shared__ float s_scale[D];
    __shared__ float s_shift[D];
    uint32_t* sAh = su + SA_H;
    uint32_t* sAl = su + SA_L;
    uint32_t* sBh = su + SB_H;
    uint32_t* sBl = su + SB_L;

    const int tid = threadIdx.x;
    const int wid = tid >> 5;
    const int lid = tid & 31;
    const int wm  = wid & 1;
    const int wn  = wid >> 1;
    const int row0 = blockIdx.x * 128;

    const uint32_t su_a = smem_u32(su);
    const uint32_t sAh_a = su_a + SA_H * 4;
    const uint32_t sAl_a = su_a + SA_L * 4;
    const uint32_t sBh_a = su_a + SB_H * 4;
    const uint32_t sBl_a = su_a + SB_L * 4;

    const int arow  = lid & 15;
    const int akoff = (lid & 16) ? 4 : 0;
    uint32_t aoff[4];
#pragma unroll
    for (int mt = 0; mt < 4; mt++)
        aoff[mt] = (uint32_t)(((wm * 64 + mt * 16 + arow) * ASTU + akoff) * 4);
    const int brow  = wn * 32 + (lid & 7) + ((lid & 16) ? 8 : 0);
    const int bkoff = (lid & 8) ? 4 : 0;
    uint32_t boff[2];
#pragma unroll
    for (int q = 0; q < 2; q++)
        boff[q] = (uint32_t)(((brow + q * 16) * BSTU + bkoff) * 4);

    // prologue: weight tiles are independent of the producer kernel
#pragma unroll
    for (int i = 0; i < 8; i++) {
        int idx = tid + i * 256;
        int r = idx >> 4;
        int q = (idx & 15) * 4;
        *(uint4*)&sBh[r * BSTU + q] = *(const uint4*)&Bh[r * 64 + q];
        *(uint4*)&sBl[r * BSTU + q] = *(const uint4*)&Bl[r * 64 + q];
    }

    // wait for producer (previous aggregate) before touching A / stats
    PDL_WAIT();

    if (apply_norm && tid < D) {
        float ts = csum[tid * 32];
        float tq = csq[tid * 32];
        float mu = ts / (float)Nn;
        float var = tq / (float)Nn - mu * mu;
        float rinv = rsqrtf(var + BN_EPS);
        float sc = rinv * gamma[tid];
        s_scale[tid] = sc;
        s_shift[tid] = beta[tid] - mu * sc;
    }
    if (apply_norm) __syncthreads();

    float acc[4][4][4];
#pragma unroll
    for (int mt = 0; mt < 4; mt++)
#pragma unroll
        for (int nt = 0; nt < 4; nt++)
#pragma unroll
            for (int i = 0; i < 4; i++) acc[mt][nt][i] = 0.0f;

    for (int p = 0; p < 2; p++) {
        if (p) __syncthreads();
#pragma unroll
        for (int i = 0; i < 8; i++) {
            int idx = tid + i * 256;
            int r = idx >> 4;
            int c4 = (idx & 15) * 4;
            float4 v = make_float4(0.f, 0.f, 0.f, 0.f);
            if (row0 + r < M)
                v = *(const float4*)&A[(size_t)(row0 + r) * 128 + p * 64 + c4];
            if (apply_norm) {
                int cg = p * 64 + c4;
                v.x = v.x * s_scale[cg]     + s_shift[cg];
                v.y = v.y * s_scale[cg + 1] + s_shift[cg + 1];
                v.z = v.z * s_scale[cg + 2] + s_shift[cg + 2];
                v.w = v.w * s_scale[cg + 3] + s_shift[cg + 3];
                v.x = v.x > 0.f ? v.x : SLOPE * v.x;
                v.y = v.y > 0.f ? v.y : SLOPE * v.y;
                v.z = v.z > 0.f ? v.z : SLOPE * v.z;
                v.w = v.w > 0.f ? v.w : SLOPE * v.w;
            }
            uint2 hp, lp;
            bf16_split_pack(v.x, v.y, hp.x, lp.x);
            bf16_split_pack(v.z, v.w, hp.y, lp.y);
            *(uint2*)&sAh[r * ASTU + (c4 >> 1)] = hp;
            *(uint2*)&sAl[r * ASTU + (c4 >> 1)] = lp;
        }
        __syncthreads();

        const uint32_t pB = (uint32_t)(p * 32 * 4);
#pragma unroll
        for (int k16 = 0; k16 < 4; k16++) {
            const uint32_t kb4 = (uint32_t)(k16 * 8 * 4);
            uint32_t af[4][4], bh[4][2], bl[4][2];
#pragma unroll
            for (int mt = 0; mt < 4; mt++)
                ldsm_x4(af[mt][0], af[mt][1], af[mt][2], af[mt][3],
                        sAh_a + aoff[mt] + kb4);
            ldsm_x4(bh[0][0], bh[0][1], bh[1][0], bh[1][1], sBh_a + boff[0] + pB + kb4);
            ldsm_x4(bh[2][0], bh[2][1], bh[3][0], bh[3][1], sBh_a + boff[1] + pB + kb4);
            ldsm_x4(bl[0][0], bl[0][1], bl[1][0], bl[1][1], sBl_a + boff[0] + pB + kb4);
            ldsm_x4(bl[2][0], bl[2][1], bl[3][0], bl[3][1], sBl_a + boff[1] + pB + kb4);
#pragma unroll
            for (int mt = 0; mt < 4; mt++)
#pragma unroll
                for (int nt = 0; nt < 4; nt++)
                    mma_bf16(acc[mt][nt], af[mt], bh[nt]);
#pragma unroll
            for (int mt = 0; mt < 4; mt++)
#pragma unroll
                for (int nt = 0; nt < 4; nt++)
                    mma_bf16(acc[mt][nt], af[mt], bl[nt]);
#pragma unroll
            for (int mt = 0; mt < 4; mt++)
                ldsm_x4(af[mt][0], af[mt][1], af[mt][2], af[mt][3],
                        sAl_a + aoff[mt] + kb4);
#pragma unroll
            for (int mt = 0; mt < 4; mt++)
#pragma unroll
                for (int nt = 0; nt < 4; nt++)
                    mma_bf16(acc[mt][nt], af[mt], bh[nt]);
        }
    }
    __syncthreads();

    const int g  = lid >> 2;
    const int tg = lid & 3;
    float* sOut = (float*)su;
#pragma unroll
    for (int mt = 0; mt < 4; mt++) {
        int r0 = wm * 64 + mt * 16 + g;
#pragma unroll
        for (int nt = 0; nt < 4; nt++) {
            int c0 = wn * 32 + nt * 8 + tg * 2;
            sOut[r0 * 129 + c0]           = acc[mt][nt][0];
            sOut[r0 * 129 + c0 + 1]       = acc[mt][nt][1];
            sOut[(r0 + 8) * 129 + c0]     = acc[mt][nt][2];
            sOut[(r0 + 8) * 129 + c0 + 1] = acc[mt][nt][3];
        }
    }
    __syncthreads();

#pragma unroll 4
    for (int i = 0; i < 64; i++) {
        int idx = tid + i * 256;
        int r = idx >> 7;
        int c = idx & 127;
        if (row0 + r < M)
            C[(size_t)(row0 + r) * 128 + c] = sOut[r * 129 + c];
    }
    PDL_TRIGGER();
}

// ---------------- weight prep + accumulator zeroing ---------------------------
__global__ void k_prep(const float* __restrict__ W1, const float* __restrict__ W2,
                       const float* __restrict__ W3) {
    __shared__ float s[32][33];
    const float* W = (blockIdx.z == 0) ? W1 : (blockIdx.z == 1) ? W2 : W3;
    uint32_t* Oh = g_WBh[blockIdx.z];
    uint32_t* Ol = g_WBl[blockIdx.z];
    int bx = blockIdx.x, by = blockIdx.y;
    int tx = threadIdx.x, ty = threadIdx.y;

    int bid = blockIdx.z * 16 + blockIdx.y * 4 + blockIdx.x;
    int gi = bid * 256 + ty * 32 + tx;
    g_colsum[0][gi] = 0.f;
    g_colsq[0][gi] = 0.f;
    if (gi < D * 32) { g_tsum[gi] = 0.f; g_tsq[gi] = 0.f; }

#pragma unroll
    for (int i = 0; i < 32; i += 8)
        s[ty + i][tx] = W[(by * 32 + ty + i) * 128 + bx * 32 + tx];
    __syncthreads();
#pragma unroll
    for (int p = ty; p < 16; p += 8) {
        float v0 = s[2 * p][tx];
        float v1 = s[2 * p + 1][tx];
        uint32_t h, l;
        bf16_split_pack(v0, v1, h, l);
        int o = (bx * 32 + tx) * 64 + by * 16 + p;
        Oh[o] = h;
        Ol[o] = l;
    }
}

// ---------------- count ---------------------------------------------------------
__global__ void k_count(const int* __restrict__ ei, const int* __restrict__ batch,
                        int E, int N) {
    int i = blockIdx.x * blockDim.x + threadIdx.x;
    if (i < E) atomicAdd(&g_deg[ei[E + i]], 1);
    if (i < N) atomicAdd(&g_gcnt[batch[i]], 1);
}

// ---------------- single fused self-cleaning scan ------------------------------
__global__ void k_scan(int N, int NC, int G) {
    __shared__ int s[CH];
    __shared__ int ticket;
    int t = threadIdx.x;
    int i = blockIdx.x * CH + t;
    int v = (i < N) ? g_deg[i] : 0;
    s[t] = v;
    __syncthreads();
    for (int off = 1; off < CH; off <<= 1) {
        int x = (t >= off) ? s[t - off] : 0;
        __syncthreads();
        s[t] += x;
        __syncthreads();
    }
    int local = s[t];
    int btotal = s[CH - 1];
    if (t == 0) {
        g_csum[blockIdx.x] = btotal;
        __threadfence();
        ticket = atomicAdd(&g_scan_cnt, 1);
    }
    __syncthreads();
    if (ticket == gridDim.x - 1) {
        int cv = (t < NC) ? g_csum[t] : 0;
        s[t] = cv;
        __syncthreads();
        for (int off = 1; off < CH; off <<= 1) {
            int x = (t >= off) ? s[t - off] : 0;
            __syncthreads();
            s[t] += x;
            __syncthreads();
        }
        if (t < NC) g_coff[t] = s[t] - cv;
        if (t == NC - 1) g_rowstart[N] = s[t];
        __syncthreads();
        int gc = (t < G) ? g_gcnt[t] : 0;
        s[t] = gc;
        __syncthreads();
        for (int off = 1; off < CH; off <<= 1) {
            int x = (t >= off) ? s[t - off] : 0;
            __syncthreads();
            s[t] += x;
            __syncthreads();
        }
        if (t < G) { g_gstart[t] = s[t] - gc; g_gcnt[t] = 0; }
        if (t == G - 1) g_gstart[G] = s[t];
        if (t == 0) g_scan_cnt = 0;
        __threadfence();
        if (t == 0) atomicExch(&g_scan_flag, 1);
    } else {
        if (t == 0) {
            while (atomicAdd(&g_scan_flag, 0) == 0) __nanosleep(64);
        }
        __syncthreads();
    }
    int co = *((volatile int*)&g_coff[blockIdx.x]);
    if (i < N) {
        int excl = co + local - v;
        g_rowstart[i] = excl;
        g_wpos[i] = excl;
        g_dinv[i] = rsqrtf((float)v + 1.0f);
        g_deg[i] = 0;
    }
    __syncthreads();
    if (t == 0) {
        int d = atomicAdd(&g_scan_done, 1);
        if (d == gridDim.x - 1) {
            g_scan_done = 0;
            atomicExch(&g_scan_flag, 0);
        }
    }
}

// ---------------- scatter: packed 8-byte payload ------------------------------
__global__ void k_scatter(const int* __restrict__ ei, int E) {
    int e = blockIdx.x * blockDim.x + threadIdx.x;
    if (e < E) {
        int s = ei[e];
        int d = ei[E + e];
        int p = atomicAdd(&g_wpos[d], 1);
        int2 pk;
        pk.x = s;
        pk.y = __float_as_int(g_dinv[s] * g_dinv[d]);
        g_edge[p] = pk;
    }
}

// ---------------- edge aggregation + fused stats partials (PDL) -----------------
__global__ void k_aggregate(const float* __restrict__ h, const float* __restrict__ bias,
                            float* __restrict__ agg, int N, int layer) {
    __shared__ float s_sum[8][132];
    __shared__ float s_sq[8][132];
    const int wid = threadIdx.x >> 5;
    const int lane = threadIdx.x & 31;
    const int node = blockIdx.x * 8 + wid;
    const float4* __restrict__ h4 = (const float4*)h;

    // CSR structures come from the side stream (complete transitively);
    // h comes from the producer GEMM -> wait before reading it.
    int j = 0, s1 = 0;
    float di = 0.f;
    if (node < N) {
        di = g_dinv[node];
        j  = g_rowstart[node];
        s1 = g_rowstart[node + 1];
    }
    PDL_WAIT();

    float4 acc0 = make_float4(0.f, 0.f, 0.f, 0.f);
    if (node < N) {
        float sc = di * di;
        float4 a = h4[(size_t)node * 32 + lane];
        acc0.x = a.x * sc; acc0.y = a.y * sc; acc0.z = a.z * sc; acc0.w = a.w * sc;
        float4 acc1 = make_float4(0.f, 0.f, 0.f, 0.f);
        float4 acc2 = make_float4(0.f, 0.f, 0.f, 0.f);
        float4 acc3 = make_float4(0.f, 0.f, 0.f, 0.f);

        for (; j + 4 <= s1; j += 4) {
            int2 e0 = g_edge[j];
            int2 e1 = g_edge[j + 1];
            int2 e2 = g_edge[j + 2];
            int2 e3 = g_edge[j + 3];
            float4 v0 = h4[(size_t)e0.x * 32 + lane];
            float4 v1 = h4[(size_t)e1.x * 32 + lane];
            float4 v2 = h4[(size_t)e2.x * 32 + lane];
            float4 v3 = h4[(size_t)e3.x * 32 + lane];
            float c0 = __int_as_float(e0.y);
            float c1 = __int_as_float(e1.y);
            float c2 = __int_as_float(e2.y);
            float c3 = __int_as_float(e3.y);
            acc0.x += v0.x * c0; acc0.y += v0.y * c0; acc0.z += v0.z * c0; acc0.w += v0.w * c0;
            acc1.x += v1.x * c1; acc1.y += v1.y * c1; acc1.z += v1.z * c1; acc1.w += v1.w * c1;
            acc2.x += v2.x * c2; acc2.y += v2.y * c2; acc2.z += v2.z * c2; acc2.w += v2.w * c2;
            acc3.x += v3.x * c3; acc3.y += v3.y * c3; acc3.z += v3.z * c3; acc3.w += v3.w * c3;
        }
        for (; j < s1; j++) {
            int2 e0 = g_edge[j];
            float c = __int_as_float(e0.y);
            float4 v = h4[(size_t)e0.x * 32 + lane];
            acc0.x += v.x * c; acc0.y += v.y * c; acc0.z += v.z * c; acc0.w += v.w * c;
        }
        float4 b = ((const float4*)bias)[lane];
        acc0.x += acc1.x + acc2.x + acc3.x + b.x;
        acc0.y += acc1.y + acc2.y + acc3.y + b.y;
        acc0.z += acc1.z + acc2.z + acc3.z + b.z;
        acc0.w += acc1.w + acc2.w + acc3.w + b.w;
        ((float4*)agg)[(size_t)node * 32 + lane] = acc0;
    }

    int c4 = lane * 4;
    s_sum[wid][c4]     = acc0.x;
    s_sum[wid][c4 + 1] = acc0.y;
    s_sum[wid][c4 + 2] = acc0.z;
    s_sum[wid][c4 + 3] = acc0.w;
    s_sq[wid][c4]      = acc0.x * acc0.x;
    s_sq[wid][c4 + 1]  = acc0.y * acc0.y;
    s_sq[wid][c4 + 2]  = acc0.z * acc0.z;
    s_sq[wid][c4 + 3]  = acc0.w * acc0.w;
    __syncthreads();

    int c = threadIdx.x;
    if (c < D) {
        float ts = 0.f, tq = 0.f;
#pragma unroll
        for (int w = 0; w < 8; w++) { ts += s_sum[w][c]; tq += s_sq[w][c]; }
        atomicAdd(&g_colsum[layer][c * 32], ts);
        atomicAdd(&g_colsq[layer][c * 32], tq);
    }
    PDL_TRIGGER();
}

// ---------------- fused tail: pool + FC1(+stats) + FC2 (PDL consumer) ----------
__device__ __forceinline__ void tail_barrier(int target) {
    __threadfence();
    __syncthreads();
    if (threadIdx.x == 0) {
        atomicAdd(&g_tail_cnt, 1);
        while (atomicAdd(&g_tail_cnt, 0) < target) __nanosleep(64);
    }
    __syncthreads();
}

__global__ void k_tail(const float* __restrict__ h, int G, int N,
                       const float* __restrict__ gamma2, const float* __restrict__ beta2,
                       const float* __restrict__ Wf1, const float* __restrict__ bf1,
                       const float* __restrict__ g4, const float* __restrict__ be4,
                       const float* __restrict__ Wf2, const float* __restrict__ bf2,
                       float* __restrict__ out) {
    __shared__ float s_scale[D], s_shift[D];
    __shared__ float As[32][36];
    __shared__ float Bs[32][132];
    __shared__ float s_sum[8][132], s_sq[8][132];
    const int tid = threadIdx.x;
    const int tx = tid & 31;
    const int ty = tid >> 5;
    const int nb = gridDim.x;
    const int row0 = blockIdx.x * 32;

    PDL_WAIT();

    if (tid < D) {
        float ts = g_colsum[2][tid * 32];
        float tq = g_colsq[2][tid * 32];
        float mu = ts / (float)N;
        float var = tq / (float)N - mu * mu;
        float rinv = rsqrtf(var + BN_EPS);
        float sc = rinv * gamma2[tid];
        s_scale[tid] = sc;
        s_shift[tid] = beta2[tid] - mu * sc;
    }
    __syncthreads();
    {
        int warp = blockIdx.x * 8 + ty;
        if (warp < G) {
            const float4* h4 = (const float4*)h;
            int c = tx * 4;
            float4 sc4 = *(float4*)&s_scale[c];
            float4 sh4 = *(float4*)&s_shift[c];
            int s0 = g_gstart[warp], s1 = g_gstart[warp + 1];
            float4 acc = make_float4(0.f, 0.f, 0.f, 0.f);
            for (int r = s0; r < s1; r++) {
                float4 v = h4[(size_t)r * 32 + tx];
                float ax = v.x * sc4.x + sh4.x;
                float ay = v.y * sc4.y + sh4.y;
                float az = v.z * sc4.z + sh4.z;
                float aw = v.w * sc4.w + sh4.w;
                acc.x += ax > 0.f ? ax : SLOPE * ax;
                acc.y += ay > 0.f ? ay : SLOPE * ay;
                acc.z += az > 0.f ? az : SLOPE * az;
                acc.w += aw > 0.f ? aw : SLOPE * aw;
            }
            int cnt = s1 - s0;
            float inv = 1.0f / (float)(cnt > 0 ? cnt : 1);
            acc.x *= inv; acc.y *= inv; acc.z *= inv; acc.w *= inv;
            ((float4*)g_pooled)[(size_t)warp * 32 + tx] = acc;
        }
    }
    tail_barrier(nb);

    if (row0 < G) {
        float acc[4][4];
#pragma unroll
        for (int i = 0; i < 4; i++)
#pragma unroll
            for (int j = 0; j < 4; j++) acc[i][j] = 0.0f;
        for (int k0 = 0; k0 < 128; k0 += 32) {
            __syncthreads();
            {
                int r = tid >> 3, c = (tid & 7) * 4;
                float4 v = make_float4(0.f, 0.f, 0.f, 0.f);
                if (row0 + r < G)
                    v = *(const float4*)&g_pooled[(size_t)(row0 + r) * 128 + k0 + c];
                As[r][c] = v.x; As[r][c + 1] = v.y; As[r][c + 2] = v.z; As[r][c + 3] = v.w;
            }
#pragma unroll
            for (int i = 0; i < 4; i++) {
                int idx = tid + i * 256;
                int r = idx >> 5, c = (idx & 31) * 4;
                float4 v = *(const float4*)&Wf1[(size_t)(k0 + r) * 128 + c];
                *(float4*)&Bs[r][c] = v;
            }
            __syncthreads();
#pragma unroll
            for (int k = 0; k < 32; k++) {
                float a[4];
#pragma unroll
                for (int i = 0; i < 4; i++) a[i] = As[ty * 4 + i][k];
                float4 b = *(const float4*)&Bs[k][tx * 4];
#pragma unroll
                for (int i = 0; i < 4; i++) {
                    acc[i][0] += a[i] * b.x;
                    acc[i][1] += a[i] * b.y;
                    acc[i][2] += a[i] * b.z;
                    acc[i][3] += a[i] * b.w;
                }
            }
        }
        float bx = bf1[tx * 4], by = bf1[tx * 4 + 1], bz = bf1[tx * 4 + 2], bw = bf1[tx * 4 + 3];
        float cs[4] = {0.f, 0.f, 0.f, 0.f};
        float cq[4] = {0.f, 0.f, 0.f, 0.f};
#pragma unroll
        for (int i = 0; i < 4; i++) {
            int r = row0 + ty * 4 + i;
            if (r < G) {
                float4 o;
                o.x = acc[i][0] + bx;
                o.y = acc[i][1] + by;
                o.z = acc[i][2] + bz;
                o.w = acc[i][3] + bw;
                *(float4*)&g_z1[(size_t)r * 128 + tx * 4] = o;
                cs[0] += o.x; cs[1] += o.y; cs[2] += o.z; cs[3] += o.w;
                cq[0] += o.x * o.x; cq[1] += o.y * o.y; cq[2] += o.z * o.z; cq[3] += o.w * o.w;
            }
        }
        __syncthreads();
#pragma unroll
        for (int j = 0; j < 4; j++) {
            s_sum[ty][tx * 4 + j] = cs[j];
            s_sq[ty][tx * 4 + j]  = cq[j];
        }
        __syncthreads();
        if (tid < D) {
            float ts = 0.f, tq = 0.f;
#pragma unroll
            for (int w = 0; w < 8; w++) { ts += s_sum[w][tid]; tq += s_sq[w][tid]; }
            atomicAdd(&g_tsum[tid * 32], ts);
            atomicAdd(&g_tsq[tid * 32], tq);
        }
    }
    tail_barrier(2 * nb);

    if (row0 < G) {
        if (tid < D) {
            float ts = g_tsum[tid * 32];
            float tq = g_tsq[tid * 32];
            float mu = ts / (float)G;
            float var = tq / (float)G - mu * mu;
            float rinv = rsqrtf(var + BN_EPS);
            float sc = rinv * g4[tid];
            s_scale[tid] = sc;
            s_shift[tid] = be4[tid] - mu * sc;
        }
        float acc[4][4];
#pragma unroll
        for (int i = 0; i < 4; i++)
#pragma unroll
            for (int j = 0; j < 4; j++) acc[i][j] = 0.0f;
        for (int k0 = 0; k0 < 128; k0 += 32) {
            __syncthreads();
            {
                int r = tid >> 3, c = (tid & 7) * 4;
                float4 v = make_float4(0.f, 0.f, 0.f, 0.f);
                if (row0 + r < G)
                    v = *(const float4*)&g_z1[(size_t)(row0 + r) * 128 + k0 + c];
                int cg = k0 + c;
                v.x = v.x * s_scale[cg]     + s_shift[cg];
                v.y = v.y * s_scale[cg + 1] + s_shift[cg + 1];
                v.z = v.z * s_scale[cg + 2] + s_shift[cg + 2];
                v.w = v.w * s_scale[cg + 3] + s_shift[cg + 3];
                v.x = v.x > 0.f ? v.x : SLOPE * v.x;
                v.y = v.y > 0.f ? v.y : SLOPE * v.y;
                v.z = v.z > 0.f ? v.z : SLOPE * v.z;
                v.w = v.w > 0.f ? v.w : SLOPE * v.w;
                As[r][c] = v.x; As[r][c + 1] = v.y; As[r][c + 2] = v.z; As[r][c + 3] = v.w;
            }
#pragma unroll
            for (int i = 0; i < 4; i++) {
                int idx = tid + i * 256;
                int r = idx >> 5, c = (idx & 31) * 4;
                float4 v = *(const float4*)&Wf2[(size_t)(k0 + r) * 128 + c];
                *(float4*)&Bs[r][c] = v;
            }
            __syncthreads();
#pragma unroll
            for (int k = 0; k < 32; k++) {
                float a[4];
#pragma unroll
                for (int i = 0; i < 4; i++) a[i] = As[ty * 4 + i][k];
                float4 b = *(const float4*)&Bs[k][tx * 4];
#pragma unroll
                for (int i = 0; i < 4; i++) {
                    acc[i][0] += a[i] * b.x;
                    acc[i][1] += a[i] * b.y;
                    acc[i][2] += a[i] * b.z;
                    acc[i][3] += a[i] * b.w;
                }
            }
        }
        float bx = bf2[tx * 4], by = bf2[tx * 4 + 1], bz = bf2[tx * 4 + 2], bw = bf2[tx * 4 + 3];
#pragma unroll
        for (int i = 0; i < 4; i++) {
            int r = row0 + ty * 4 + i;
            if (r < G) {
                float4 o;
                o.x = acc[i][0] + bx;
                o.y = acc[i][1] + by;
                o.z = acc[i][2] + bz;
                o.w = acc[i][3] + bw;
                *(float4*)&out[(size_t)r * 128 + tx * 4] = o;
            }
        }
    }

    __syncthreads();
    if (tid == 0) {
        int d = atomicAdd(&g_tail_done, 1);
        if (d == nb - 1) {
            g_tail_done = 0;
            atomicExch(&g_tail_cnt, 0);
        }
    }
}

// ---------------- driver ---------------------------------------------------------
extern "C" void kernel_launch(void* const* d_in, const int* in_sizes, int n_in,
                              void* d_out, int out_size) {
    const float* x      = (const float*)d_in[0];
    const int*   ei     = (const int*)d_in[1];
    const int*   batch  = (const int*)d_in[2];
    const float* W1  = (const float*)d_in[4];
    const float* b1  = (const float*)d_in[5];
    const float* g1  = (const float*)d_in[6];
    const float* be1 = (const float*)d_in[7];
    const float* W2  = (const float*)d_in[8];
    const float* b2  = (const float*)d_in[9];
    const float* g2  = (const float*)d_in[10];
    const float* be2 = (const float*)d_in[11];
    const float* W3  = (const float*)d_in[12];
    const float* b3  = (const float*)d_in[13];
    const float* g3  = (const float*)d_in[14];
    const float* be3 = (const float*)d_in[15];
    const float* Wf1 = (const float*)d_in[16];
    const float* bf1 = (const float*)d_in[17];
    const float* g4  = (const float*)d_in[18];
    const float* be4 = (const float*)d_in[19];
    const float* Wf2 = (const float*)d_in[20];
    const float* bf2 = (const float*)d_in[21];

    int N = in_sizes[0] / D;
    int E = in_sizes[1] / 2;
    int G = out_size / D;
    if (N > NMAX || E > EMAX || G > GMAX) return;

    cudaFuncSetAttribute(k_gemm_bf16, cudaFuncAttributeMaxDynamicSharedMemorySize,
                         GEMM_U32 * 4);

    float *buf1, *buf2;
    float *csum, *csq;
    uint32_t *wbh, *wbl;
    cudaGetSymbolAddress((void**)&buf1, g_buf1);
    cudaGetSymbolAddress((void**)&buf2, g_buf2);
    cudaGetSymbolAddress((void**)&wbh, g_WBh);
    cudaGetSymbolAddress((void**)&wbl, g_WBl);
    cudaGetSymbolAddress((void**)&csum, g_colsum);
    cudaGetSymbolAddress((void**)&csq, g_colsq);

    int NC = (N + CH - 1) / CH;
    int mx = max(E, N);

    static cudaStream_t sB = nullptr;
    static cudaEvent_t evFork = nullptr, evCSR = nullptr;
    if (sB == nullptr) {
        cudaStreamCreateWithFlags(&sB, cudaStreamNonBlocking);
        cudaEventCreateWithFlags(&evFork, cudaEventDisableTiming);
        cudaEventCreateWithFlags(&evCSR, cudaEventDisableTiming);
    }

    cudaEventRecord(evFork, 0);
    cudaStreamWaitEvent(sB, evFork, 0);
    k_count<<<(mx + 255) / 256, 256, 0, sB>>>(ei, batch, E, N);
    k_scan<<<NC, CH, 0, sB>>>(N, NC, G);
    k_scatter<<<(E + 255) / 256, 256, 0, sB>>>(ei, E);
    cudaEventRecord(evCSR, sB);

    const float* bs[3]  = {b1, b2, b3};
    const float* gs[3]  = {g1, g2, g3};
    const float* bes[3] = {be1, be2, be3};

    int tc_grid    = (N + 127) / 128;
    int agg_blocks = (N + 7) / 8;

    k_prep<<<dim3(4, 4, 3), dim3(32, 8)>>>(W1, W2, W3);
    k_gemm_bf16<<<tc_grid, 256, GEMM_U32 * 4>>>(x, wbh, wbl, buf1, N, 0,
                                                nullptr, nullptr, nullptr, nullptr, N);

    cudaStreamWaitEvent(0, evCSR, 0);

    // PDL launch helper
    cudaLaunchAttribute pdlAttr[1];
    pdlAttr[0].id = cudaLaunchAttributeProgrammaticStreamSerialization;
    pdlAttr[0].val.programmaticStreamSerializationAllowed = 1;

    for (int L = 0; L < 3; L++) {
        if (L > 0) {
            cudaLaunchConfig_t cfg = {};
            cfg.gridDim = dim3(tc_grid);
            cfg.blockDim = dim3(256);
            cfg.dynamicSmemBytes = GEMM_U32 * 4;
            cfg.stream = 0;
            cfg.attrs = pdlAttr;
            cfg.numAttrs = 1;
            const float* cs_p = csum + (L - 1) * D * 32;
            const float* cq_p = csq + (L - 1) * D * 32;
            const uint32_t* bh_p = wbh + L * D * 64;
            const uint32_t* bl_p = wbl + L * D * 64;
            const float* A_p = buf2;
            float* C_p = buf1;
            int an = 1;
            cudaLaunchKernelEx(&cfg, k_gemm_bf16, A_p, bh_p, bl_p, C_p, N, an,
                               cs_p, cq_p, gs[L - 1], bes[L - 1], N);
        }
        {
            cudaLaunchConfig_t cfg = {};
            cfg.gridDim = dim3(agg_blocks);
            cfg.blockDim = dim3(256);
            cfg.dynamicSmemBytes = 0;
            cfg.stream = 0;
            cfg.attrs = pdlAttr;
            cfg.numAttrs = 1;
            const float* h_p = buf1;
            float* agg_p = buf2;
            cudaLaunchKernelEx(&cfg, k_aggregate, h_p, bs[L], agg_p, N, L);
        }
    }

    {
        int tb = (G + 7) / 8;
        cudaLaunchConfig_t cfg = {};
        cfg.gridDim = dim3(tb);
        cfg.blockDim = dim3(256);
        cfg.dynamicSmemBytes = 0;
        cfg.stream = 0;
        cfg.attrs = pdlAttr;
        cfg.numAttrs = 1;
        const float* h_p = buf2;
        float* out_p = (float*)d_out;
        cudaLaunchKernelEx(&cfg, k_tail, h_p, G, N, gs[2], bes[2], Wf1, bf1,
                           g4, be4, Wf2, bf2, out_p);
    }
}